// round 9
// baseline (speedup 1.0000x reference)
#include <cuda_runtime.h>
#include <math.h>

#define NN   20000
#define E1C  100000
#define E2C  100000
#define HN   (NN*128)
#define CUTV 6.0f
#define PI_F 3.14159265358979f
#define XSL  196   /* 32x196 floats; 196%32=4 banks -> conflict-free te access */

#define NB0  3125
#define NB1  625
#define NB2  3125
#define NBT  (NB0+NB1+NB2)

typedef unsigned long long u64t;

/* ---------------- persistent device scratch ---------------- */
__device__ __align__(16) float g_WcT[256*128];
__device__ __align__(16) float g_Wc2dT[64*128];
__device__ __align__(16) float g_WcrbfT[64*128];
__device__ __align__(16) float g_etb[3*128];
__device__ __align__(16) float g_cvec[128];
__device__ __align__(16) float g_nproj[(size_t)2*NN*128];
/* qc-contiguous phase-C weights: [qc][k 0..191][ch 0..127]
   k<128: W_phi2 slice; k>=128: W_msg slice */
__device__ __align__(16) float g_WallT[3*192*128];
__device__ unsigned char g_mask[NN];

/* -------- packed f32x2 helpers (.b64 regs via "l") -------- */
__device__ __forceinline__ u64t fma2d(u64t a, u64t b, u64t c) {
    u64t d; asm("fma.rn.f32x2 %0, %1, %2, %3;" : "=l"(d) : "l"(a), "l"(b), "l"(c));
    return d;
}
__device__ __forceinline__ u64t splat2(float x) {
    u64t d; asm("mov.b64 %0, {%1, %1};" : "=l"(d) : "r"(__float_as_uint(x)));
    return d;
}
__device__ __forceinline__ u64t fadd2(u64t a, u64t b) { return fma2d(a, splat2(1.0f), b); }
__device__ __forceinline__ u64t fmul2(u64t a, u64t b) { return fma2d(a, b, splat2(0.0f)); }
__device__ __forceinline__ float lo2(u64t d) { return __uint_as_float((unsigned)(d & 0xffffffffull)); }
__device__ __forceinline__ float hi2(u64t d) { return __uint_as_float((unsigned)(d >> 32)); }
__device__ __forceinline__ void red4(float* p, float a, float b, float c, float d) {
    asm volatile("red.global.add.v4.f32 [%0], {%1, %2, %3, %4};"
                 :: "l"(p), "f"(a), "f"(b), "f"(c), "f"(d) : "memory");
}

/* ---------------- fused precompute ---------------- */
__global__ void k_pre(const float* __restrict__ W_i, const float* __restrict__ W_phi1,
                      const float* __restrict__ b_phi1, const float* __restrict__ W_e2d,
                      const float* __restrict__ W_rbf, const float* __restrict__ ET,
                      const float* __restrict__ virt,
                      const float* __restrict__ W_phi2, const float* __restrict__ W_msg)
{
    int b = blockIdx.x;
    int t = threadIdx.x;
    if (b < 194) {
        int idx = b*256 + t;
        if (idx < NN) g_mask[idx] = 0;
        if (idx < 32768) {
            int k = idx >> 7, p = idx & 127;
            float s = 0.f;
            #pragma unroll 4
            for (int j = 0; j < 128; j++) s += W_phi1[p*288 + j] * W_i[j*256 + k];
            g_WcT[idx] = s;
        } else if (idx < 40960) {
            int i = idx - 32768; int k = i >> 7, p = i & 127;
            float s = 0.f;
            #pragma unroll 4
            for (int j = 0; j < 128; j++) s += W_phi1[p*288 + 128 + j] * W_e2d[j*64 + k];
            g_Wc2dT[i] = s;
        } else if (idx < 49152) {
            int i = idx - 40960; int k = i >> 7, p = i & 127;
            float s = 0.f;
            #pragma unroll 4
            for (int j = 0; j < 128; j++) s += W_phi1[p*288 + 128 + j] * W_rbf[j*64 + k];
            g_WcrbfT[i] = s;
        } else if (idx < 49536) {
            int i = idx - 49152; int tt = i >> 7, p = i & 127;
            float s = b_phi1[p];
            #pragma unroll
            for (int l = 0; l < 32; l++) s += W_phi1[p*288 + 256 + l] * ET[tt*32 + l];
            g_etb[i] = s;
        }
    } else if (b == 194) {
        __shared__ float u[128];
        if (t < 128) {
            float s = 0.f;
            #pragma unroll 4
            for (int j = 0; j < 128; j++) s += W_i[t*256 + 128 + j] * virt[j];
            u[t] = s;
        }
        __syncthreads();
        if (t < 128) {
            float c = 0.f;
            #pragma unroll 4
            for (int q = 0; q < 128; q++) c += W_phi1[t*288 + q] * u[q];
            g_cvec[t] = c;
        }
    } else {
        int idx = (b - 195)*256 + t;
        if (idx < 3*192*128) {
            int qc = idx / (192*128);
            int r  = idx % (192*128);
            int k  = r >> 7, ch = r & 127;
            float v;
            if (k < 128) v = W_phi2[(size_t)(qc*128 + ch)*128 + k];
            else         v = W_msg [(size_t)(qc*128 + ch)*64 + (k - 128)];
            g_WallT[idx] = v;
        }
    }
}

__global__ void k_maskset(const int* __restrict__ Edist_idx)
{
    int idx = blockIdx.x*256 + threadIdx.x;
    if (idx < 2*E2C) g_mask[Edist_idx[idx]] = 1;
}

/* ---------------- node projection ---------------- */
__global__ void __launch_bounds__(128) k_nproj(const float* __restrict__ H,
                                               const float* __restrict__ H2d)
{
    __shared__ float hx[16*128];
    __shared__ float h2[16*128];
    int t = threadIdx.x;
    int i0 = blockIdx.x * 16;
    #pragma unroll
    for (int it = 0; it < 16; it++) {
        int idx = t + it*128;
        int nd = idx >> 7, p = idx & 127;
        hx[idx] = H  [(size_t)(i0+nd)*128 + p];
        h2[idx] = H2d[(size_t)(i0+nd)*128 + p];
    }
    __syncthreads();
    float a1[16], a2[16];
    #pragma unroll
    for (int nd = 0; nd < 16; nd++) { a1[nd] = 0.f; a2[nd] = 0.f; }
    for (int kk = 0; kk < 128; kk += 4) {
        float w0 = g_WcT[(kk+0)*128+t], w1 = g_WcT[(kk+1)*128+t];
        float w2 = g_WcT[(kk+2)*128+t], w3 = g_WcT[(kk+3)*128+t];
        float v0 = g_WcT[(128+kk+0)*128+t], v1 = g_WcT[(128+kk+1)*128+t];
        float v2 = g_WcT[(128+kk+2)*128+t], v3 = g_WcT[(128+kk+3)*128+t];
        #pragma unroll
        for (int nd = 0; nd < 16; nd++) {
            float4 f = *(const float4*)&hx[nd*128 + kk];
            a1[nd] += f.x*w0 + f.y*w1 + f.z*w2 + f.w*w3;
            float4 g = *(const float4*)&h2[nd*128 + kk];
            a2[nd] += g.x*v0 + g.y*v1 + g.z*v2 + g.w*v3;
        }
    }
    float cv = g_cvec[t];
    #pragma unroll
    for (int nd = 0; nd < 16; nd++) {
        g_nproj[(size_t)(i0+nd)*128 + t]    = a1[nd] + a2[nd];
        g_nproj[(size_t)(NN+i0+nd)*128 + t] = a1[nd] + cv;
    }
}

/* ------- GEMM micro-kernel: weights LDG-direct, 2 quads x 4 edges, K=64 ------- */
__device__ __forceinline__ void gemm64g(const float* __restrict__ W, int ldw,
                                        const float* __restrict__ xsp,
                                        int c0, int c1, u64t (&acc)[4][4])
{
    #pragma unroll 2
    for (int k4 = 0; k4 < 64; k4 += 4) {
        float4 xv[4];
        #pragma unroll
        for (int j = 0; j < 4; j++)
            xv[j] = *(const float4*)(xsp + j*(4*XSL) + k4);
        #pragma unroll
        for (int kk = 0; kk < 4; kk++) {
            ulonglong2 wA = *(const ulonglong2*)(W + (size_t)(k4+kk)*ldw + c0);
            ulonglong2 wB = *(const ulonglong2*)(W + (size_t)(k4+kk)*ldw + c1);
            #pragma unroll
            for (int j = 0; j < 4; j++) {
                u64t a = splat2(((const float*)&xv[j])[kk]);
                acc[0][j] = fma2d(a, wA.x, acc[0][j]);
                acc[1][j] = fma2d(a, wA.y, acc[1][j]);
                acc[2][j] = fma2d(a, wB.x, acc[2][j]);
                acc[3][j] = fma2d(a, wB.y, acc[3][j]);
            }
        }
    }
}

/* ---------------- fused per-edge kernel: 32 edges / 128 threads ---------------- */
__global__ void __launch_bounds__(128, 3) k_edge(
    const int* __restrict__ E2d_idx, const float* __restrict__ E2d_feat,
    const int* __restrict__ Edist_idx, const float* __restrict__ Edist_val,
    const float* __restrict__ Z, const float* __restrict__ Z3d,
    const float* __restrict__ V,
    const float* __restrict__ b_phi2, const float* __restrict__ b_msg,
    float* __restrict__ out)
{
    extern __shared__ float sm[];
    float* smxs = sm;                       /* 32 x 196 */
    int*   srow = (int*)(sm + 32*XSL);
    int*   scol = srow + 32;
    float* sdist = (float*)(scol + 32);
    float* senvd = sdist + 32;
    float* sdval = senvd + 32;
    float* senv2 = sdval + 32;
    float* sunit = senv2 + 32;              /* 32 x 3 */

    int t  = threadIdx.x;
    int w  = t >> 5;
    int l  = t & 31;
    int tp = l & 7;
    int te = l >> 3;                /* 0..3 */
    int cb = (w & 1) * 64;
    int eb = (w >> 1) * 16;
    int c0 = cb + tp*4;
    int c1 = cb + 32 + tp*4;
    int ebte = eb + te;             /* thread edges: ebte + 4*j */

    int bid = blockIdx.x;
    int base = bid * 32;
    int type = (bid < NB0) ? 0 : (bid < NB0+NB1 ? 1 : 2);

    /* --- metadata + geometry (warp 0) --- */
    if (t < 32) {
        int eg = base + t;
        int row, col; float dval = 0.f;
        if (type == 0)      { row = E2d_idx[eg]; col = E2d_idx[E1C + eg]; }
        else if (type == 1) { int i = eg - E1C; row = i; col = NN + i; }
        else                { int j = eg - E1C - NN; row = Edist_idx[j];
                              col = Edist_idx[E2C + j]; dval = Edist_val[j]; }
        srow[t] = row; scol[t] = col; sdval[t] = dval;
        float zr0 = Z[row*3+0], zr1 = Z[row*3+1], zr2 = Z[row*3+2];
        float zc0, zc1, zc2;
        if (col < NN) { zc0 = Z[col*3+0]; zc1 = Z[col*3+1]; zc2 = Z[col*3+2]; }
        else { int c2 = col - NN; zc0 = Z3d[c2*3+0]; zc1 = Z3d[c2*3+1]; zc2 = Z3d[c2*3+2]; }
        float r0 = zr0-zc0, r1 = zr1-zc1, r2 = zr2-zc2;
        float d = sqrtf(r0*r0 + r1*r1 + r2*r2 + 1e-8f);
        sdist[t] = d;
        float inv = 1.0f / d;
        sunit[t*3+0] = r0*inv; sunit[t*3+1] = r1*inv; sunit[t*3+2] = r2*inv;
        float cl = fminf(d * (1.0f/CUTV), 1.0f);
        senvd[t] = 0.5f * (cosf(PI_F*cl) + 1.0f);
        float cl2 = fminf(fmaxf(dval * (1.0f/CUTV), 0.f), 1.0f);
        senv2[t] = 0.5f * (cosf(PI_F*cl2) + 1.0f);
    }
    __syncthreads();

    /* --- per-edge 64-dim features into xs[e][128..191] --- */
    const float cstep = CUTV / 63.0f;
    const float i2w2  = 1.0f / (2.0f * (CUTV/64.0f) * (CUTV/64.0f));
    if (type == 0) {
        #pragma unroll
        for (int it = 0; it < 16; it++) {
            int idx = t + it*128; int e = idx & 31, k = idx >> 5;
            smxs[e*XSL + 128 + k] = E2d_feat[(size_t)k*E1C + base + e];
        }
    } else if (type == 2) {
        #pragma unroll
        for (int it = 0; it < 16; it++) {
            int idx = t + it*128; int e = idx & 31, k = idx >> 5;
            float diff = sdval[e] - k*cstep;
            smxs[e*XSL + 128 + k] = expf(-diff*diff*i2w2) * senv2[e];
        }
    }
    /* --- gather node projection + edge-type bias --- */
    u64t gn[4][4];
    #pragma unroll
    for (int j = 0; j < 4; j++) {
        const float* np = g_nproj + (size_t)scol[ebte + 4*j]*128;
        ulonglong2 ga = *(const ulonglong2*)(np + c0);
        ulonglong2 gb = *(const ulonglong2*)(np + c1);
        gn[0][j] = ga.x; gn[1][j] = ga.y; gn[2][j] = gb.x; gn[3][j] = gb.y;
    }
    u64t et2[4];
    {
        ulonglong2 ea = *(const ulonglong2*)(g_etb + type*128 + c0);
        ulonglong2 eb2 = *(const ulonglong2*)(g_etb + type*128 + c1);
        et2[0] = ea.x; et2[1] = ea.y; et2[2] = eb2.x; et2[3] = eb2.y;
    }
    __syncthreads();

    /* --- phase A: act = nproj[col] + etb (+ feats @ Wtype^T); silu --- */
    {
        u64t acc[4][4] = {};
        if (type == 0)
            gemm64g(g_Wc2dT, 128, smxs + ebte*XSL + 128, c0, c1, acc);
        else if (type == 2)
            gemm64g(g_WcrbfT, 128, smxs + ebte*XSL + 128, c0, c1, acc);
        #pragma unroll
        for (int j = 0; j < 4; j++) {
            int e = ebte + 4*j;
            float v[8];
            #pragma unroll
            for (int q = 0; q < 4; q++) {
                u64t s = fadd2(acc[q][j], fadd2(gn[q][j], et2[q]));
                float a = lo2(s), b = hi2(s);
                v[2*q]   = a / (1.0f + expf(-a));
                v[2*q+1] = b / (1.0f + expf(-b));
            }
            *(float4*)&smxs[e*XSL + c0] = make_float4(v[0], v[1], v[2], v[3]);
            *(float4*)&smxs[e*XSL + c1] = make_float4(v[4], v[5], v[6], v[7]);
        }
    }
    __syncthreads();

    /* --- geometric RBF overwrites feats --- */
    #pragma unroll
    for (int it = 0; it < 16; it++) {
        int idx = t + it*128; int e = idx & 31, k = idx >> 5;
        float diff = sdist[e] - k*cstep;
        smxs[e*XSL + 128 + k] = expf(-diff*diff*i2w2) * senvd[e];
    }
    __syncthreads();

    /* --- phase C (sync-free): qc order {1,2,0}; weights qc-contiguous --- */
    u64t vg2[4][4];
    #pragma unroll 1
    for (int qi = 0; qi < 3; qi++) {
        int qc = (qi == 0) ? 1 : (qi == 1 ? 2 : 0);
        const float* Wq = g_WallT + (size_t)qc*(192*128);
        u64t accp[4][4] = {};
        gemm64g(Wq,            128, smxs + ebte*XSL,       c0, c1, accp);
        gemm64g(Wq + 64*128,   128, smxs + ebte*XSL + 64,  c0, c1, accp);
        u64t accw[4][4] = {};
        gemm64g(Wq + 128*128,  128, smxs + ebte*XSL + 128, c0, c1, accw);

        u64t bpp[4], bmm[4];
        {
            ulonglong2 a = *(const ulonglong2*)(b_phi2 + qc*128 + c0);
            ulonglong2 b = *(const ulonglong2*)(b_phi2 + qc*128 + c1);
            bpp[0] = a.x; bpp[1] = a.y; bpp[2] = b.x; bpp[3] = b.y;
            ulonglong2 c = *(const ulonglong2*)(b_msg + qc*128 + c0);
            ulonglong2 d = *(const ulonglong2*)(b_msg + qc*128 + c1);
            bmm[0] = c.x; bmm[1] = c.y; bmm[2] = d.x; bmm[3] = d.y;
        }
        u64t m2[4][4];
        #pragma unroll
        for (int q = 0; q < 4; q++)
            #pragma unroll
            for (int j = 0; j < 4; j++)
                m2[q][j] = fmul2(fadd2(accp[q][j], bpp[q]),
                                 fadd2(accw[q][j], bmm[q]));

        if (qc == 1) {
            #pragma unroll
            for (int q = 0; q < 4; q++)
                #pragma unroll
                for (int j = 0; j < 4; j++)
                    vg2[q][j] = m2[q][j];
        } else if (qc == 2) {
            #pragma unroll
            for (int j = 0; j < 4; j++) {
                int e = ebte + 4*j;
                int row = srow[e], col = scol[e];
                float u0 = sunit[e*3+0], u1 = sunit[e*3+1], u2 = sunit[e*3+2];
                float vb[24];
                if (type != 1) {
                    const float4* vpa = (const float4*)(V + (size_t)col*384 + c0*3);
                    const float4* vpb = (const float4*)(V + (size_t)col*384 + c1*3);
                    #pragma unroll
                    for (int q = 0; q < 3; q++) { ((float4*)vb)[q] = vpa[q]; ((float4*)vb)[3+q] = vpb[q]; }
                } else {
                    #pragma unroll
                    for (int q = 0; q < 24; q++) vb[q] = 0.f;
                }
                float dv[24];
                #pragma unroll
                for (int h = 0; h < 2; h++) {
                    #pragma unroll
                    for (int cq = 0; cq < 4; cq++) {
                        u64t vgw = vg2[h*2 + (cq>>1)][j];
                        u64t rgw = m2 [h*2 + (cq>>1)][j];
                        float vg = (cq & 1) ? hi2(vgw) : lo2(vgw);
                        float rg = (cq & 1) ? hi2(rgw) : lo2(rgw);
                        int b = h*12 + cq*3;
                        dv[b+0] = vb[b+0]*vg + u0*rg;
                        dv[b+1] = vb[b+1]*vg + u1*rg;
                        dv[b+2] = vb[b+2]*vg + u2*rg;
                    }
                }
                float* opa = out + HN + (size_t)row*384 + c0*3;
                float* opb = out + HN + (size_t)row*384 + c1*3;
                #pragma unroll
                for (int q = 0; q < 3; q++) {
                    red4(opa + q*4, dv[q*4+0],    dv[q*4+1],    dv[q*4+2],    dv[q*4+3]);
                    red4(opb + q*4, dv[12+q*4+0], dv[12+q*4+1], dv[12+q*4+2], dv[12+q*4+3]);
                }
            }
        } else { /* qc == 0 : H scatter */
            #pragma unroll
            for (int j = 0; j < 4; j++) {
                float* hp = out + (size_t)srow[ebte + 4*j]*128;
                red4(hp + c0, lo2(m2[0][j]), hi2(m2[0][j]), lo2(m2[1][j]), hi2(m2[1][j]));
                red4(hp + c1, lo2(m2[2][j]), hi2(m2[2][j]), lo2(m2[3][j]), hi2(m2[3][j]));
            }
        }
    }
}

/* ---------------- finalize ---------------- */
__global__ void k_fin(float* __restrict__ out,
                      const unsigned char* __restrict__ m2d,
                      const unsigned char* __restrict__ m3d, int total)
{
    int idx = blockIdx.x*256 + threadIdx.x;
    if (idx >= total) return;
    int i = (idx < HN) ? (idx >> 7) : ((idx - HN) / 384);
    float v = out[idx];
    v = fminf(fmaxf(v, -100.f), 100.f);
    bool keep = ((m2d[i] | m3d[i] | g_mask[i]) != 0);
    out[idx] = keep ? v : 0.f;
}

#define SMEM_EDGE ((32*XSL + 2*32 + 4*32 + 96 + 32) * sizeof(float))

extern "C" void kernel_launch(void* const* d_in, const int* in_sizes, int n_in,
                              void* d_out, int out_size)
{
    int o = (in_sizes[3] == 1) ? 1 : 0;
    const float* H      = (const float*)d_in[0];
    const float* V      = (const float*)d_in[1];
    const float* Z      = (const float*)d_in[2];
    const float* H2d    = (const float*)d_in[3+o];
    const unsigned char* m2d = (const unsigned char*)d_in[4+o];
    const int*   E2didx = (const int*)d_in[5+o];
    const float* E2dfeat= (const float*)d_in[6+o];
    const float* Z3d    = (const float*)d_in[7+o];
    const unsigned char* m3d = (const unsigned char*)d_in[8+o];
    const int*   Edidx  = (const int*)d_in[9+o];
    const float* Edval  = (const float*)d_in[10+o];
    const float* virt   = (const float*)d_in[11+o];
    const float* ETe    = (const float*)d_in[12+o];
    const float* Wrbf   = (const float*)d_in[13+o];
    const float* We2d   = (const float*)d_in[14+o];
    const float* Wi     = (const float*)d_in[15+o];
    const float* Wphi1  = (const float*)d_in[16+o];
    const float* bphi1  = (const float*)d_in[17+o];
    const float* Wphi2  = (const float*)d_in[18+o];
    const float* bphi2  = (const float*)d_in[19+o];
    const float* Wmsg   = (const float*)d_in[20+o];
    const float* bmsg   = (const float*)d_in[21+o];
    float* out = (float*)d_out;

    cudaMemsetAsync(d_out, 0, (size_t)out_size * sizeof(float));
    k_pre<<<483, 256>>>(Wi, Wphi1, bphi1, We2d, Wrbf, ETe, virt, Wphi2, Wmsg);
    k_maskset<<<782, 256>>>(Edidx);
    k_nproj<<<1250, 128>>>(H, H2d);
    cudaFuncSetAttribute(k_edge, cudaFuncAttributeMaxDynamicSharedMemorySize,
                         (int)SMEM_EDGE);
    k_edge<<<NBT, 128, SMEM_EDGE>>>(E2didx, E2dfeat, Edidx, Edval, Z, Z3d, V,
                                    bphi2, bmsg, out);
    k_fin<<<(HN + 3*HN + 255)/256, 256>>>(out, m2d, m3d, HN + 3*HN);
}

// round 10
// speedup vs baseline: 1.0324x; 1.0324x over previous
#include <cuda_runtime.h>
#include <math.h>

#define NN   20000
#define E1C  100000
#define E2C  100000
#define HN   (NN*128)
#define CUTV 6.0f
#define PI_F 3.14159265358979f
#define XSL  196   /* 32x196 floats; 196%32=4 banks -> conflict-free te access */
#define VGL  132   /* vg buffer stride; 132%32=4 -> conflict-free */

#define NB0  3125
#define NB1  625
#define NB2  3125
#define NBT  (NB0+NB1+NB2)

typedef unsigned long long u64t;

/* ---------------- persistent device scratch ---------------- */
__device__ __align__(16) float g_WcT[256*128];
__device__ __align__(16) float g_Wc2dT[64*128];
__device__ __align__(16) float g_WcrbfT[64*128];
__device__ __align__(16) float g_etb[3*128];
__device__ __align__(16) float g_cvec[128];
__device__ __align__(16) float g_nproj[(size_t)2*NN*128];
/* qc-contiguous phase-C weights: [qc][k 0..191][ch 0..127] */
__device__ __align__(16) float g_WallT[3*192*128];
__device__ unsigned char g_mask[NN];

/* -------- packed f32x2 helpers (.b64 regs via "l") -------- */
__device__ __forceinline__ u64t fma2d(u64t a, u64t b, u64t c) {
    u64t d; asm("fma.rn.f32x2 %0, %1, %2, %3;" : "=l"(d) : "l"(a), "l"(b), "l"(c));
    return d;
}
__device__ __forceinline__ u64t splat2(float x) {
    u64t d; asm("mov.b64 %0, {%1, %1};" : "=l"(d) : "r"(__float_as_uint(x)));
    return d;
}
__device__ __forceinline__ u64t fadd2(u64t a, u64t b) { return fma2d(a, splat2(1.0f), b); }
__device__ __forceinline__ u64t fmul2(u64t a, u64t b) { return fma2d(a, b, splat2(0.0f)); }
__device__ __forceinline__ float lo2(u64t d) { return __uint_as_float((unsigned)(d & 0xffffffffull)); }
__device__ __forceinline__ float hi2(u64t d) { return __uint_as_float((unsigned)(d >> 32)); }
__device__ __forceinline__ void red4(float* p, float a, float b, float c, float d) {
    asm volatile("red.global.add.v4.f32 [%0], {%1, %2, %3, %4};"
                 :: "l"(p), "f"(a), "f"(b), "f"(c), "f"(d) : "memory");
}

/* ---------------- fused precompute ---------------- */
__global__ void k_pre(const float* __restrict__ W_i, const float* __restrict__ W_phi1,
                      const float* __restrict__ b_phi1, const float* __restrict__ W_e2d,
                      const float* __restrict__ W_rbf, const float* __restrict__ ET,
                      const float* __restrict__ virt,
                      const float* __restrict__ W_phi2, const float* __restrict__ W_msg)
{
    int b = blockIdx.x;
    int t = threadIdx.x;
    if (b < 194) {
        int idx = b*256 + t;
        if (idx < NN) g_mask[idx] = 0;
        if (idx < 32768) {
            int k = idx >> 7, p = idx & 127;
            float s = 0.f;
            #pragma unroll 4
            for (int j = 0; j < 128; j++) s += W_phi1[p*288 + j] * W_i[j*256 + k];
            g_WcT[idx] = s;
        } else if (idx < 40960) {
            int i = idx - 32768; int k = i >> 7, p = i & 127;
            float s = 0.f;
            #pragma unroll 4
            for (int j = 0; j < 128; j++) s += W_phi1[p*288 + 128 + j] * W_e2d[j*64 + k];
            g_Wc2dT[i] = s;
        } else if (idx < 49152) {
            int i = idx - 40960; int k = i >> 7, p = i & 127;
            float s = 0.f;
            #pragma unroll 4
            for (int j = 0; j < 128; j++) s += W_phi1[p*288 + 128 + j] * W_rbf[j*64 + k];
            g_WcrbfT[i] = s;
        } else if (idx < 49536) {
            int i = idx - 49152; int tt = i >> 7, p = i & 127;
            float s = b_phi1[p];
            #pragma unroll
            for (int l = 0; l < 32; l++) s += W_phi1[p*288 + 256 + l] * ET[tt*32 + l];
            g_etb[i] = s;
        }
    } else if (b == 194) {
        __shared__ float u[128];
        if (t < 128) {
            float s = 0.f;
            #pragma unroll 4
            for (int j = 0; j < 128; j++) s += W_i[t*256 + 128 + j] * virt[j];
            u[t] = s;
        }
        __syncthreads();
        if (t < 128) {
            float c = 0.f;
            #pragma unroll 4
            for (int q = 0; q < 128; q++) c += W_phi1[t*288 + q] * u[q];
            g_cvec[t] = c;
        }
    } else {
        int idx = (b - 195)*256 + t;
        if (idx < 3*192*128) {
            int qc = idx / (192*128);
            int r  = idx % (192*128);
            int k  = r >> 7, ch = r & 127;
            float v;
            if (k < 128) v = W_phi2[(size_t)(qc*128 + ch)*128 + k];
            else         v = W_msg [(size_t)(qc*128 + ch)*64 + (k - 128)];
            g_WallT[idx] = v;
        }
    }
}

__global__ void k_maskset(const int* __restrict__ Edist_idx)
{
    int idx = blockIdx.x*256 + threadIdx.x;
    if (idx < 2*E2C) g_mask[Edist_idx[idx]] = 1;
}

/* ---------------- node projection ---------------- */
__global__ void __launch_bounds__(128) k_nproj(const float* __restrict__ H,
                                               const float* __restrict__ H2d)
{
    __shared__ float hx[16*128];
    __shared__ float h2[16*128];
    int t = threadIdx.x;
    int i0 = blockIdx.x * 16;
    #pragma unroll
    for (int it = 0; it < 16; it++) {
        int idx = t + it*128;
        int nd = idx >> 7, p = idx & 127;
        hx[idx] = H  [(size_t)(i0+nd)*128 + p];
        h2[idx] = H2d[(size_t)(i0+nd)*128 + p];
    }
    __syncthreads();
    float a1[16], a2[16];
    #pragma unroll
    for (int nd = 0; nd < 16; nd++) { a1[nd] = 0.f; a2[nd] = 0.f; }
    for (int kk = 0; kk < 128; kk += 4) {
        float w0 = g_WcT[(kk+0)*128+t], w1 = g_WcT[(kk+1)*128+t];
        float w2 = g_WcT[(kk+2)*128+t], w3 = g_WcT[(kk+3)*128+t];
        float v0 = g_WcT[(128+kk+0)*128+t], v1 = g_WcT[(128+kk+1)*128+t];
        float v2 = g_WcT[(128+kk+2)*128+t], v3 = g_WcT[(128+kk+3)*128+t];
        #pragma unroll
        for (int nd = 0; nd < 16; nd++) {
            float4 f = *(const float4*)&hx[nd*128 + kk];
            a1[nd] += f.x*w0 + f.y*w1 + f.z*w2 + f.w*w3;
            float4 g = *(const float4*)&h2[nd*128 + kk];
            a2[nd] += g.x*v0 + g.y*v1 + g.z*v2 + g.w*v3;
        }
    }
    float cv = g_cvec[t];
    #pragma unroll
    for (int nd = 0; nd < 16; nd++) {
        g_nproj[(size_t)(i0+nd)*128 + t]    = a1[nd] + a2[nd];
        g_nproj[(size_t)(NN+i0+nd)*128 + t] = a1[nd] + cv;
    }
}

/* ------- GEMM micro-kernel: weights LDG-direct, 2 quads x 4 edges, K=64 ------- */
__device__ __forceinline__ void gemm64g(const float* __restrict__ W, int ldw,
                                        const float* __restrict__ xsp,
                                        int c0, int c1, u64t (&acc)[4][4])
{
    #pragma unroll 2
    for (int k4 = 0; k4 < 64; k4 += 4) {
        float4 xv[4];
        #pragma unroll
        for (int j = 0; j < 4; j++)
            xv[j] = *(const float4*)(xsp + j*(4*XSL) + k4);
        #pragma unroll
        for (int kk = 0; kk < 4; kk++) {
            ulonglong2 wA = *(const ulonglong2*)(W + (size_t)(k4+kk)*ldw + c0);
            ulonglong2 wB = *(const ulonglong2*)(W + (size_t)(k4+kk)*ldw + c1);
            #pragma unroll
            for (int j = 0; j < 4; j++) {
                u64t a = splat2(((const float*)&xv[j])[kk]);
                acc[0][j] = fma2d(a, wA.x, acc[0][j]);
                acc[1][j] = fma2d(a, wA.y, acc[1][j]);
                acc[2][j] = fma2d(a, wB.x, acc[2][j]);
                acc[3][j] = fma2d(a, wB.y, acc[3][j]);
            }
        }
    }
}

/* ---------------- fused per-edge kernel: 32 edges / 128 threads ---------------- */
__global__ void __launch_bounds__(128, 4) k_edge(
    const int* __restrict__ E2d_idx, const float* __restrict__ E2d_feat,
    const int* __restrict__ Edist_idx, const float* __restrict__ Edist_val,
    const float* __restrict__ Z, const float* __restrict__ Z3d,
    const float* __restrict__ V,
    const float* __restrict__ b_phi2, const float* __restrict__ b_msg,
    float* __restrict__ out)
{
    extern __shared__ float sm[];
    float* smxs  = sm;                        /* 32 x 196 */
    float* vgbuf = sm + 32*XSL;               /* 32 x 132 */
    int*   srow  = (int*)(vgbuf + 32*VGL);
    int*   scol  = srow + 32;
    float* sdist = (float*)(scol + 32);
    float* senvd = sdist + 32;
    float* sdval = senvd + 32;
    float* senv2 = sdval + 32;
    float* sunit = senv2 + 32;                /* 32 x 3 */

    int t  = threadIdx.x;
    int w  = t >> 5;
    int l  = t & 31;
    int tp = l & 7;
    int te = l >> 3;                /* 0..3 */
    int cb = (w & 1) * 64;
    int eb = (w >> 1) * 16;
    int c0 = cb + tp*4;
    int c1 = cb + 32 + tp*4;
    int ebte = eb + te;             /* thread edges: ebte + 4*j */

    int bid = blockIdx.x;
    int base = bid * 32;
    int type = (bid < NB0) ? 0 : (bid < NB0+NB1 ? 1 : 2);

    /* --- metadata + geometry (warp 0) --- */
    if (t < 32) {
        int eg = base + t;
        int row, col; float dval = 0.f;
        if (type == 0)      { row = E2d_idx[eg]; col = E2d_idx[E1C + eg]; }
        else if (type == 1) { int i = eg - E1C; row = i; col = NN + i; }
        else                { int j = eg - E1C - NN; row = Edist_idx[j];
                              col = Edist_idx[E2C + j]; dval = Edist_val[j]; }
        srow[t] = row; scol[t] = col; sdval[t] = dval;
        float zr0 = Z[row*3+0], zr1 = Z[row*3+1], zr2 = Z[row*3+2];
        float zc0, zc1, zc2;
        if (col < NN) { zc0 = Z[col*3+0]; zc1 = Z[col*3+1]; zc2 = Z[col*3+2]; }
        else { int c2 = col - NN; zc0 = Z3d[c2*3+0]; zc1 = Z3d[c2*3+1]; zc2 = Z3d[c2*3+2]; }
        float r0 = zr0-zc0, r1 = zr1-zc1, r2 = zr2-zc2;
        float d = sqrtf(r0*r0 + r1*r1 + r2*r2 + 1e-8f);
        sdist[t] = d;
        float inv = 1.0f / d;
        sunit[t*3+0] = r0*inv; sunit[t*3+1] = r1*inv; sunit[t*3+2] = r2*inv;
        float cl = fminf(d * (1.0f/CUTV), 1.0f);
        senvd[t] = 0.5f * (cosf(PI_F*cl) + 1.0f);
        float cl2 = fminf(fmaxf(dval * (1.0f/CUTV), 0.f), 1.0f);
        senv2[t] = 0.5f * (cosf(PI_F*cl2) + 1.0f);
    }
    __syncthreads();

    /* --- per-edge 64-dim features into xs[e][128..191] --- */
    const float cstep = CUTV / 63.0f;
    const float i2w2  = 1.0f / (2.0f * (CUTV/64.0f) * (CUTV/64.0f));
    if (type == 0) {
        #pragma unroll
        for (int it = 0; it < 16; it++) {
            int idx = t + it*128; int e = idx & 31, k = idx >> 5;
            smxs[e*XSL + 128 + k] = E2d_feat[(size_t)k*E1C + base + e];
        }
    } else if (type == 2) {
        #pragma unroll
        for (int it = 0; it < 16; it++) {
            int idx = t + it*128; int e = idx & 31, k = idx >> 5;
            float diff = sdval[e] - k*cstep;
            smxs[e*XSL + 128 + k] = expf(-diff*diff*i2w2) * senv2[e];
        }
    }
    /* --- gather node projection + edge-type bias --- */
    u64t gn[4][4];
    #pragma unroll
    for (int j = 0; j < 4; j++) {
        const float* np = g_nproj + (size_t)scol[ebte + 4*j]*128;
        ulonglong2 ga = *(const ulonglong2*)(np + c0);
        ulonglong2 gb = *(const ulonglong2*)(np + c1);
        gn[0][j] = ga.x; gn[1][j] = ga.y; gn[2][j] = gb.x; gn[3][j] = gb.y;
    }
    u64t et2[4];
    {
        ulonglong2 ea = *(const ulonglong2*)(g_etb + type*128 + c0);
        ulonglong2 eb2 = *(const ulonglong2*)(g_etb + type*128 + c1);
        et2[0] = ea.x; et2[1] = ea.y; et2[2] = eb2.x; et2[3] = eb2.y;
    }
    __syncthreads();

    /* --- phase A: act = nproj[col] + etb (+ feats @ Wtype^T); silu --- */
    {
        u64t acc[4][4] = {};
        if (type == 0)
            gemm64g(g_Wc2dT, 128, smxs + ebte*XSL + 128, c0, c1, acc);
        else if (type == 2)
            gemm64g(g_WcrbfT, 128, smxs + ebte*XSL + 128, c0, c1, acc);
        #pragma unroll
        for (int j = 0; j < 4; j++) {
            int e = ebte + 4*j;
            float v[8];
            #pragma unroll
            for (int q = 0; q < 4; q++) {
                u64t s = fadd2(acc[q][j], fadd2(gn[q][j], et2[q]));
                float a = lo2(s), b = hi2(s);
                v[2*q]   = a / (1.0f + expf(-a));
                v[2*q+1] = b / (1.0f + expf(-b));
            }
            *(float4*)&smxs[e*XSL + c0] = make_float4(v[0], v[1], v[2], v[3]);
            *(float4*)&smxs[e*XSL + c1] = make_float4(v[4], v[5], v[6], v[7]);
        }
    }
    __syncthreads();

    /* --- geometric RBF overwrites feats --- */
    #pragma unroll
    for (int it = 0; it < 16; it++) {
        int idx = t + it*128; int e = idx & 31, k = idx >> 5;
        float diff = sdist[e] - k*cstep;
        smxs[e*XSL + 128 + k] = expf(-diff*diff*i2w2) * senvd[e];
    }
    __syncthreads();

    /* --- phase C (sync-free): qc order {1,2,0}; vg spilled to smem --- */
    #pragma unroll 1
    for (int qi = 0; qi < 3; qi++) {
        int qc = (qi == 0) ? 1 : (qi == 1 ? 2 : 0);
        const float* Wq = g_WallT + (size_t)qc*(192*128);
        u64t accp[4][4] = {};
        gemm64g(Wq,            128, smxs + ebte*XSL,       c0, c1, accp);
        gemm64g(Wq + 64*128,   128, smxs + ebte*XSL + 64,  c0, c1, accp);
        u64t accw[4][4] = {};
        gemm64g(Wq + 128*128,  128, smxs + ebte*XSL + 128, c0, c1, accw);

        u64t bpp[4], bmm[4];
        {
            ulonglong2 a = *(const ulonglong2*)(b_phi2 + qc*128 + c0);
            ulonglong2 b = *(const ulonglong2*)(b_phi2 + qc*128 + c1);
            bpp[0] = a.x; bpp[1] = a.y; bpp[2] = b.x; bpp[3] = b.y;
            ulonglong2 c = *(const ulonglong2*)(b_msg + qc*128 + c0);
            ulonglong2 d = *(const ulonglong2*)(b_msg + qc*128 + c1);
            bmm[0] = c.x; bmm[1] = c.y; bmm[2] = d.x; bmm[3] = d.y;
        }
        u64t m2[4][4];
        #pragma unroll
        for (int q = 0; q < 4; q++)
            #pragma unroll
            for (int j = 0; j < 4; j++)
                m2[q][j] = fmul2(fadd2(accp[q][j], bpp[q]),
                                 fadd2(accw[q][j], bmm[q]));

        if (qc == 1) {
            /* store vg to smem (thread-private slots; no sync needed) */
            #pragma unroll
            for (int j = 0; j < 4; j++) {
                int e = ebte + 4*j;
                *(float4*)&vgbuf[e*VGL + c0] =
                    make_float4(lo2(m2[0][j]), hi2(m2[0][j]), lo2(m2[1][j]), hi2(m2[1][j]));
                *(float4*)&vgbuf[e*VGL + c1] =
                    make_float4(lo2(m2[2][j]), hi2(m2[2][j]), lo2(m2[3][j]), hi2(m2[3][j]));
            }
        } else if (qc == 2) {
            #pragma unroll
            for (int j = 0; j < 4; j++) {
                int e = ebte + 4*j;
                int row = srow[e], col = scol[e];
                float u0 = sunit[e*3+0], u1 = sunit[e*3+1], u2 = sunit[e*3+2];
                float vb[24];
                if (type != 1) {
                    const float4* vpa = (const float4*)(V + (size_t)col*384 + c0*3);
                    const float4* vpb = (const float4*)(V + (size_t)col*384 + c1*3);
                    #pragma unroll
                    for (int q = 0; q < 3; q++) { ((float4*)vb)[q] = vpa[q]; ((float4*)vb)[3+q] = vpb[q]; }
                } else {
                    #pragma unroll
                    for (int q = 0; q < 24; q++) vb[q] = 0.f;
                }
                float4 vga = *(const float4*)&vgbuf[e*VGL + c0];
                float4 vgb = *(const float4*)&vgbuf[e*VGL + c1];
                const float* vgaf = (const float*)&vga;
                const float* vgbf = (const float*)&vgb;
                float dv[24];
                #pragma unroll
                for (int h = 0; h < 2; h++) {
                    #pragma unroll
                    for (int cq = 0; cq < 4; cq++) {
                        u64t rgw = m2[h*2 + (cq>>1)][j];
                        float vg = h ? vgbf[cq] : vgaf[cq];
                        float rg = (cq & 1) ? hi2(rgw) : lo2(rgw);
                        int b = h*12 + cq*3;
                        dv[b+0] = vb[b+0]*vg + u0*rg;
                        dv[b+1] = vb[b+1]*vg + u1*rg;
                        dv[b+2] = vb[b+2]*vg + u2*rg;
                    }
                }
                float* opa = out + HN + (size_t)row*384 + c0*3;
                float* opb = out + HN + (size_t)row*384 + c1*3;
                #pragma unroll
                for (int q = 0; q < 3; q++) {
                    red4(opa + q*4, dv[q*4+0],    dv[q*4+1],    dv[q*4+2],    dv[q*4+3]);
                    red4(opb + q*4, dv[12+q*4+0], dv[12+q*4+1], dv[12+q*4+2], dv[12+q*4+3]);
                }
            }
        } else { /* qc == 0 : H scatter */
            #pragma unroll
            for (int j = 0; j < 4; j++) {
                float* hp = out + (size_t)srow[ebte + 4*j]*128;
                red4(hp + c0, lo2(m2[0][j]), hi2(m2[0][j]), lo2(m2[1][j]), hi2(m2[1][j]));
                red4(hp + c1, lo2(m2[2][j]), hi2(m2[2][j]), lo2(m2[3][j]), hi2(m2[3][j]));
            }
        }
    }
}

/* ---------------- finalize ---------------- */
__global__ void k_fin(float* __restrict__ out,
                      const unsigned char* __restrict__ m2d,
                      const unsigned char* __restrict__ m3d, int total)
{
    int idx = blockIdx.x*256 + threadIdx.x;
    if (idx >= total) return;
    int i = (idx < HN) ? (idx >> 7) : ((idx - HN) / 384);
    float v = out[idx];
    v = fminf(fmaxf(v, -100.f), 100.f);
    bool keep = ((m2d[i] | m3d[i] | g_mask[i]) != 0);
    out[idx] = keep ? v : 0.f;
}

#define SMEM_EDGE ((32*XSL + 32*VGL + 2*32 + 4*32 + 96 + 32) * sizeof(float))

extern "C" void kernel_launch(void* const* d_in, const int* in_sizes, int n_in,
                              void* d_out, int out_size)
{
    int o = (in_sizes[3] == 1) ? 1 : 0;
    const float* H      = (const float*)d_in[0];
    const float* V      = (const float*)d_in[1];
    const float* Z      = (const float*)d_in[2];
    const float* H2d    = (const float*)d_in[3+o];
    const unsigned char* m2d = (const unsigned char*)d_in[4+o];
    const int*   E2didx = (const int*)d_in[5+o];
    const float* E2dfeat= (const float*)d_in[6+o];
    const float* Z3d    = (const float*)d_in[7+o];
    const unsigned char* m3d = (const unsigned char*)d_in[8+o];
    const int*   Edidx  = (const int*)d_in[9+o];
    const float* Edval  = (const float*)d_in[10+o];
    const float* virt   = (const float*)d_in[11+o];
    const float* ETe    = (const float*)d_in[12+o];
    const float* Wrbf   = (const float*)d_in[13+o];
    const float* We2d   = (const float*)d_in[14+o];
    const float* Wi     = (const float*)d_in[15+o];
    const float* Wphi1  = (const float*)d_in[16+o];
    const float* bphi1  = (const float*)d_in[17+o];
    const float* Wphi2  = (const float*)d_in[18+o];
    const float* bphi2  = (const float*)d_in[19+o];
    const float* Wmsg   = (const float*)d_in[20+o];
    const float* bmsg   = (const float*)d_in[21+o];
    float* out = (float*)d_out;

    cudaMemsetAsync(d_out, 0, (size_t)out_size * sizeof(float));
    k_pre<<<483, 256>>>(Wi, Wphi1, bphi1, We2d, Wrbf, ETe, virt, Wphi2, Wmsg);
    k_maskset<<<782, 256>>>(Edidx);
    k_nproj<<<1250, 128>>>(H, H2d);
    cudaFuncSetAttribute(k_edge, cudaFuncAttributeMaxDynamicSharedMemorySize,
                         (int)SMEM_EDGE);
    k_edge<<<NBT, 128, SMEM_EDGE>>>(E2didx, E2dfeat, Edidx, Edval, Z, Z3d, V,
                                    bphi2, bmsg, out);
    k_fin<<<(HN + 3*HN + 255)/256, 256>>>(out, m2d, m3d, HN + 3*HN);
}

// round 11
// speedup vs baseline: 1.5397x; 1.4914x over previous
#include <cuda_runtime.h>
#include <math.h>

#define NN   20000
#define E1C  100000
#define E2C  100000
#define HN   (NN*128)
#define CUTV 6.0f
#define PI_F 3.14159265358979f
#define XSL  196   /* 32x196 fp32 xs rows */
#define VGL  132   /* vg buffer stride */

#define NB0  3125
#define NB1  625
#define NB2  3125
#define NBT  (NB0+NB1+NB2)

typedef unsigned long long u64t;

/* ---------------- persistent device scratch ---------------- */
__device__ __align__(16) float g_WcT[256*128];
__device__ __align__(16) float g_Wc2dT[64*128];
__device__ __align__(16) float g_WcrbfT[64*128];
__device__ __align__(16) float g_etb[3*128];
__device__ __align__(16) float g_cvec[128];
__device__ __align__(16) float g_nproj[(size_t)2*NN*128];
/* pre-swizzled bf16 B fragments: [qc(3)][kt(12)][ntile(16)][lane(32)] x uint2 */
__device__ __align__(16) uint2 g_WfH[576*32];
__device__ __align__(16) uint2 g_WfL[576*32];
__device__ unsigned char g_mask[NN];

/* -------- packed f32x2 helpers -------- */
__device__ __forceinline__ u64t fma2d(u64t a, u64t b, u64t c) {
    u64t d; asm("fma.rn.f32x2 %0, %1, %2, %3;" : "=l"(d) : "l"(a), "l"(b), "l"(c));
    return d;
}
__device__ __forceinline__ u64t splat2(float x) {
    u64t d; asm("mov.b64 %0, {%1, %1};" : "=l"(d) : "r"(__float_as_uint(x)));
    return d;
}
__device__ __forceinline__ u64t fadd2(u64t a, u64t b) { return fma2d(a, splat2(1.0f), b); }
__device__ __forceinline__ float lo2(u64t d) { return __uint_as_float((unsigned)(d & 0xffffffffull)); }
__device__ __forceinline__ float hi2(u64t d) { return __uint_as_float((unsigned)(d >> 32)); }
__device__ __forceinline__ void red2(float* p, float a, float b) {
    asm volatile("red.global.add.v2.f32 [%0], {%1, %2};" :: "l"(p), "f"(a), "f"(b) : "memory");
}
/* bf16x2 pack: low half = x, high half = y; plus hi/lo split */
__device__ __forceinline__ void bfsplit2(float x, float y, unsigned& hi, unsigned& lo) {
    unsigned h; asm("cvt.rn.bf16x2.f32 %0, %1, %2;" : "=r"(h) : "f"(y), "f"(x));
    float xh = __uint_as_float(h << 16);
    float yh = __uint_as_float(h & 0xffff0000u);
    asm("cvt.rn.bf16x2.f32 %0, %1, %2;" : "=r"(lo) : "f"(y - yh), "f"(x - xh));
    hi = h;
}
/* ldmatrix x4 (A fragment, row-major) */
__device__ __forceinline__ void ldmA(unsigned a[4], unsigned saddr) {
    asm volatile("ldmatrix.sync.aligned.m8n8.x4.shared.b16 {%0,%1,%2,%3}, [%4];"
                 : "=r"(a[0]), "=r"(a[1]), "=r"(a[2]), "=r"(a[3]) : "r"(saddr));
}
/* mma m16n8k16 bf16, fp32 acc */
__device__ __forceinline__ void mmabf(float* d, const unsigned a[4], uint2 b) {
    asm volatile("mma.sync.aligned.m16n8k16.row.col.f32.bf16.bf16.f32 "
                 "{%0,%1,%2,%3}, {%4,%5,%6,%7}, {%8,%9}, {%0,%1,%2,%3};"
                 : "+f"(d[0]), "+f"(d[1]), "+f"(d[2]), "+f"(d[3])
                 : "r"(a[0]), "r"(a[1]), "r"(a[2]), "r"(a[3]), "r"(b.x), "r"(b.y));
}

/* ---------------- fused precompute ---------------- */
__global__ void k_pre(const float* __restrict__ W_i, const float* __restrict__ W_phi1,
                      const float* __restrict__ b_phi1, const float* __restrict__ W_e2d,
                      const float* __restrict__ W_rbf, const float* __restrict__ ET,
                      const float* __restrict__ virt,
                      const float* __restrict__ W_phi2, const float* __restrict__ W_msg)
{
    int b = blockIdx.x;
    int t = threadIdx.x;
    if (b < 194) {
        int idx = b*256 + t;
        if (idx < NN) g_mask[idx] = 0;
        if (idx < 32768) {
            int k = idx >> 7, p = idx & 127;
            float s = 0.f;
            #pragma unroll 4
            for (int j = 0; j < 128; j++) s += W_phi1[p*288 + j] * W_i[j*256 + k];
            g_WcT[idx] = s;
        } else if (idx < 40960) {
            int i = idx - 32768; int k = i >> 7, p = i & 127;
            float s = 0.f;
            #pragma unroll 4
            for (int j = 0; j < 128; j++) s += W_phi1[p*288 + 128 + j] * W_e2d[j*64 + k];
            g_Wc2dT[i] = s;
        } else if (idx < 49152) {
            int i = idx - 40960; int k = i >> 7, p = i & 127;
            float s = 0.f;
            #pragma unroll 4
            for (int j = 0; j < 128; j++) s += W_phi1[p*288 + 128 + j] * W_rbf[j*64 + k];
            g_WcrbfT[i] = s;
        } else if (idx < 49536) {
            int i = idx - 49152; int tt = i >> 7, p = i & 127;
            float s = b_phi1[p];
            #pragma unroll
            for (int l = 0; l < 32; l++) s += W_phi1[p*288 + 256 + l] * ET[tt*32 + l];
            g_etb[i] = s;
        }
    } else if (b == 194) {
        __shared__ float u[128];
        if (t < 128) {
            float s = 0.f;
            #pragma unroll 4
            for (int j = 0; j < 128; j++) s += W_i[t*256 + 128 + j] * virt[j];
            u[t] = s;
        }
        __syncthreads();
        if (t < 128) {
            float c = 0.f;
            #pragma unroll 4
            for (int q = 0; q < 128; q++) c += W_phi1[t*288 + q] * u[q];
            g_cvec[t] = c;
        }
    } else {
        /* B fragment build: idx over 576 records x 32 lanes x 2 halves */
        int idx = (b - 195)*256 + t;
        if (idx < 36864) {
            int rec  = idx >> 6;
            int wi   = idx & 63;
            int lane = wi >> 1;
            int half = wi & 1;
            int nt = rec & 15;
            int kt = (rec >> 4) % 12;
            int qc = rec / 192;
            int ch = qc*128 + nt*8 + (lane >> 2);
            int k0 = kt*16 + (lane & 3)*2 + half*8;
            float w0, w1;
            if (k0 < 128) {
                w0 = W_phi2[(size_t)ch*128 + k0];
                w1 = W_phi2[(size_t)ch*128 + k0 + 1];
            } else {
                w0 = W_msg[(size_t)ch*64 + k0 - 128];
                w1 = W_msg[(size_t)ch*64 + k0 - 127];
            }
            unsigned hi, lo;
            bfsplit2(w0, w1, hi, lo);
            ((unsigned*)g_WfH)[rec*64 + lane*2 + half] = hi;
            ((unsigned*)g_WfL)[rec*64 + lane*2 + half] = lo;
        }
    }
}

__global__ void k_maskset(const int* __restrict__ Edist_idx)
{
    int idx = blockIdx.x*256 + threadIdx.x;
    if (idx < 2*E2C) g_mask[Edist_idx[idx]] = 1;
}

/* ---------------- node projection ---------------- */
__global__ void __launch_bounds__(128) k_nproj(const float* __restrict__ H,
                                               const float* __restrict__ H2d)
{
    __shared__ float hx[16*128];
    __shared__ float h2[16*128];
    int t = threadIdx.x;
    int i0 = blockIdx.x * 16;
    #pragma unroll
    for (int it = 0; it < 16; it++) {
        int idx = t + it*128;
        int nd = idx >> 7, p = idx & 127;
        hx[idx] = H  [(size_t)(i0+nd)*128 + p];
        h2[idx] = H2d[(size_t)(i0+nd)*128 + p];
    }
    __syncthreads();
    float a1[16], a2[16];
    #pragma unroll
    for (int nd = 0; nd < 16; nd++) { a1[nd] = 0.f; a2[nd] = 0.f; }
    for (int kk = 0; kk < 128; kk += 4) {
        float w0 = g_WcT[(kk+0)*128+t], w1 = g_WcT[(kk+1)*128+t];
        float w2 = g_WcT[(kk+2)*128+t], w3 = g_WcT[(kk+3)*128+t];
        float v0 = g_WcT[(128+kk+0)*128+t], v1 = g_WcT[(128+kk+1)*128+t];
        float v2 = g_WcT[(128+kk+2)*128+t], v3 = g_WcT[(128+kk+3)*128+t];
        #pragma unroll
        for (int nd = 0; nd < 16; nd++) {
            float4 f = *(const float4*)&hx[nd*128 + kk];
            a1[nd] += f.x*w0 + f.y*w1 + f.z*w2 + f.w*w3;
            float4 g = *(const float4*)&h2[nd*128 + kk];
            a2[nd] += g.x*v0 + g.y*v1 + g.z*v2 + g.w*v3;
        }
    }
    float cv = g_cvec[t];
    #pragma unroll
    for (int nd = 0; nd < 16; nd++) {
        g_nproj[(size_t)(i0+nd)*128 + t]    = a1[nd] + a2[nd];
        g_nproj[(size_t)(NN+i0+nd)*128 + t] = a1[nd] + cv;
    }
}

/* ------- fp32 GEMM micro-kernel (phase A only) ------- */
__device__ __forceinline__ void gemm64g(const float* __restrict__ W, int ldw,
                                        const float* __restrict__ xsp,
                                        int c0, int c1, u64t (&acc)[4][4])
{
    #pragma unroll 2
    for (int k4 = 0; k4 < 64; k4 += 4) {
        float4 xv[4];
        #pragma unroll
        for (int j = 0; j < 4; j++)
            xv[j] = *(const float4*)(xsp + j*(4*XSL) + k4);
        #pragma unroll
        for (int kk = 0; kk < 4; kk++) {
            ulonglong2 wA = *(const ulonglong2*)(W + (size_t)(k4+kk)*ldw + c0);
            ulonglong2 wB = *(const ulonglong2*)(W + (size_t)(k4+kk)*ldw + c1);
            #pragma unroll
            for (int j = 0; j < 4; j++) {
                u64t a = splat2(((const float*)&xv[j])[kk]);
                acc[0][j] = fma2d(a, wA.x, acc[0][j]);
                acc[1][j] = fma2d(a, wA.y, acc[1][j]);
                acc[2][j] = fma2d(a, wB.x, acc[2][j]);
                acc[3][j] = fma2d(a, wB.y, acc[3][j]);
            }
        }
    }
}

/* ---------------- fused per-edge kernel: 32 edges / 128 threads ---------------- */
__global__ void __launch_bounds__(128, 3) k_edge(
    const int* __restrict__ E2d_idx, const float* __restrict__ E2d_feat,
    const int* __restrict__ Edist_idx, const float* __restrict__ Edist_val,
    const float* __restrict__ Z, const float* __restrict__ Z3d,
    const float* __restrict__ V,
    const float* __restrict__ b_phi2, const float* __restrict__ b_msg,
    float* __restrict__ out)
{
    extern __shared__ float sm[];
    float*    smxs  = sm;                             /* 32 x 196 fp32 */
    float*    vgbuf = sm + 32*XSL;                    /* 32 x 132 */
    unsigned* xshiw = (unsigned*)(vgbuf + 32*VGL);    /* 32 x 100 u32 (bf16x2) */
    unsigned* xslow = xshiw + 3200;                   /* 32 x 100 u32 */
    int*   srow  = (int*)(xslow + 3200);
    int*   scol  = srow + 32;
    float* sdist = (float*)(scol + 32);
    float* senvd = sdist + 32;
    float* sdval = senvd + 32;
    float* senv2 = sdval + 32;
    float* sunit = senv2 + 32;                        /* 32 x 3 */

    int t  = threadIdx.x;
    int w  = t >> 5;
    int l  = t & 31;
    /* phase A mapping */
    int tp = l & 7;
    int te = l >> 3;
    int cb = (w & 1) * 64;
    int eb = (w >> 1) * 16;
    int c0 = cb + tp*4;
    int c1 = cb + 32 + tp*4;
    int ebte = eb + te;

    int bid = blockIdx.x;
    int base = bid * 32;
    int type = (bid < NB0) ? 0 : (bid < NB0+NB1 ? 1 : 2);

    /* --- metadata + geometry (warp 0) --- */
    if (t < 32) {
        int eg = base + t;
        int row, col; float dval = 0.f;
        if (type == 0)      { row = E2d_idx[eg]; col = E2d_idx[E1C + eg]; }
        else if (type == 1) { int i = eg - E1C; row = i; col = NN + i; }
        else                { int j = eg - E1C - NN; row = Edist_idx[j];
                              col = Edist_idx[E2C + j]; dval = Edist_val[j]; }
        srow[t] = row; scol[t] = col; sdval[t] = dval;
        float zr0 = Z[row*3+0], zr1 = Z[row*3+1], zr2 = Z[row*3+2];
        float zc0, zc1, zc2;
        if (col < NN) { zc0 = Z[col*3+0]; zc1 = Z[col*3+1]; zc2 = Z[col*3+2]; }
        else { int c2 = col - NN; zc0 = Z3d[c2*3+0]; zc1 = Z3d[c2*3+1]; zc2 = Z3d[c2*3+2]; }
        float r0 = zr0-zc0, r1 = zr1-zc1, r2 = zr2-zc2;
        float d = sqrtf(r0*r0 + r1*r1 + r2*r2 + 1e-8f);
        sdist[t] = d;
        float inv = 1.0f / d;
        sunit[t*3+0] = r0*inv; sunit[t*3+1] = r1*inv; sunit[t*3+2] = r2*inv;
        float cl = fminf(d * (1.0f/CUTV), 1.0f);
        senvd[t] = 0.5f * (cosf(PI_F*cl) + 1.0f);
        float cl2 = fminf(fmaxf(dval * (1.0f/CUTV), 0.f), 1.0f);
        senv2[t] = 0.5f * (cosf(PI_F*cl2) + 1.0f);
    }
    __syncthreads();

    /* --- per-edge 64-dim features into xs[e][128..191] --- */
    const float cstep = CUTV / 63.0f;
    const float i2w2  = 1.0f / (2.0f * (CUTV/64.0f) * (CUTV/64.0f));
    if (type == 0) {
        #pragma unroll
        for (int it = 0; it < 16; it++) {
            int idx = t + it*128; int e = idx & 31, k = idx >> 5;
            smxs[e*XSL + 128 + k] = E2d_feat[(size_t)k*E1C + base + e];
        }
    } else if (type == 2) {
        #pragma unroll
        for (int it = 0; it < 16; it++) {
            int idx = t + it*128; int e = idx & 31, k = idx >> 5;
            float diff = sdval[e] - k*cstep;
            smxs[e*XSL + 128 + k] = expf(-diff*diff*i2w2) * senv2[e];
        }
    }
    /* --- gather node projection + edge-type bias --- */
    u64t gn[4][4];
    #pragma unroll
    for (int j = 0; j < 4; j++) {
        const float* np = g_nproj + (size_t)scol[ebte + 4*j]*128;
        ulonglong2 ga = *(const ulonglong2*)(np + c0);
        ulonglong2 gb = *(const ulonglong2*)(np + c1);
        gn[0][j] = ga.x; gn[1][j] = ga.y; gn[2][j] = gb.x; gn[3][j] = gb.y;
    }
    u64t et2[4];
    {
        ulonglong2 ea = *(const ulonglong2*)(g_etb + type*128 + c0);
        ulonglong2 eb2 = *(const ulonglong2*)(g_etb + type*128 + c1);
        et2[0] = ea.x; et2[1] = ea.y; et2[2] = eb2.x; et2[3] = eb2.y;
    }
    __syncthreads();

    /* --- phase A (fp32): act = nproj[col] + etb (+ feats @ Wtype^T); silu --- */
    {
        u64t acc[4][4] = {};
        if (type == 0)
            gemm64g(g_Wc2dT, 128, smxs + ebte*XSL + 128, c0, c1, acc);
        else if (type == 2)
            gemm64g(g_WcrbfT, 128, smxs + ebte*XSL + 128, c0, c1, acc);
        #pragma unroll
        for (int j = 0; j < 4; j++) {
            int e = ebte + 4*j;
            float v[8];
            #pragma unroll
            for (int q = 0; q < 4; q++) {
                u64t s = fadd2(acc[q][j], fadd2(gn[q][j], et2[q]));
                float a = lo2(s), b = hi2(s);
                v[2*q]   = a / (1.0f + expf(-a));
                v[2*q+1] = b / (1.0f + expf(-b));
            }
            *(float4*)&smxs[e*XSL + c0] = make_float4(v[0], v[1], v[2], v[3]);
            *(float4*)&smxs[e*XSL + c1] = make_float4(v[4], v[5], v[6], v[7]);
        }
    }
    __syncthreads();

    /* --- geometric RBF overwrites feats --- */
    #pragma unroll
    for (int it = 0; it < 16; it++) {
        int idx = t + it*128; int e = idx & 31, k = idx >> 5;
        float diff = sdist[e] - k*cstep;
        smxs[e*XSL + 128 + k] = expf(-diff*diff*i2w2) * senvd[e];
    }
    __syncthreads();

    /* --- convert xs fp32 -> bf16 hi/lo (rows padded to 200 bf16 = 400B) --- */
    #pragma unroll
    for (int it = 0; it < 24; it++) {
        int lin = t + it*128;          /* 0..3071 */
        int e  = lin / 96;
        int kp = lin % 96;
        float2 v = *(const float2*)&smxs[e*XSL + kp*2];
        unsigned hi, lo;
        bfsplit2(v.x, v.y, hi, lo);
        xshiw[e*100 + kp] = hi;
        xslow[e*100 + kp] = lo;
    }
    __syncthreads();

    /* --- phase C: bf16x3 tensor-core GEMM + fused scatter; qc order {1,2,0} --- */
    unsigned xshi_s = (unsigned)__cvta_generic_to_shared(xshiw);
    unsigned xslo_s = (unsigned)__cvta_generic_to_shared(xslow);
    unsigned a_off  = (unsigned)((l & 15)*400 + (l >> 4)*16);

    #pragma unroll 1
    for (int qi = 0; qi < 3; qi++) {
        int qc = (qi == 0) ? 1 : (qi == 1 ? 2 : 0);
        float accP[2][4][4], accW[2][4][4];
        #pragma unroll
        for (int mt = 0; mt < 2; mt++)
            #pragma unroll
            for (int nt = 0; nt < 4; nt++)
                #pragma unroll
                for (int r = 0; r < 4; r++) { accP[mt][nt][r] = 0.f; accW[mt][nt][r] = 0.f; }

        #pragma unroll 1
        for (int pass = 0; pass < 3; pass++) {
            unsigned As = (pass == 2) ? xslo_s : xshi_s;
            const uint2* Wf = ((pass == 1) ? g_WfL : g_WfH) + l;
            int recb = (qc*12)*16 + (w << 2);
            #pragma unroll
            for (int kt = 0; kt < 12; kt++) {
                unsigned a0[4], a1[4];
                ldmA(a0, As + a_off + kt*32);
                ldmA(a1, As + a_off + kt*32 + 6400);
                #pragma unroll
                for (int nt = 0; nt < 4; nt++) {
                    uint2 bfr = Wf[(size_t)(recb + kt*16 + nt)*32];
                    if (kt < 8) { mmabf(accP[0][nt], a0, bfr); mmabf(accP[1][nt], a1, bfr); }
                    else        { mmabf(accW[0][nt], a0, bfr); mmabf(accW[1][nt], a1, bfr); }
                }
            }
        }

        /* epilogue */
        #pragma unroll
        for (int nt = 0; nt < 4; nt++) {
            int ch0 = (w << 5) + (nt << 3) + ((l & 3) << 1);
            float2 bp = *(const float2*)&b_phi2[qc*128 + ch0];
            float2 bm = *(const float2*)&b_msg [qc*128 + ch0];
            #pragma unroll
            for (int mt = 0; mt < 2; mt++) {
                float m0 = (accP[mt][nt][0] + bp.x) * (accW[mt][nt][0] + bm.x);
                float m1 = (accP[mt][nt][1] + bp.y) * (accW[mt][nt][1] + bm.y);
                float m2 = (accP[mt][nt][2] + bp.x) * (accW[mt][nt][2] + bm.x);
                float m3 = (accP[mt][nt][3] + bp.y) * (accW[mt][nt][3] + bm.y);
                int e1 = (mt << 4) + (l >> 2);
                int e2 = e1 + 8;
                if (qc == 1) {
                    *(float2*)&vgbuf[e1*VGL + ch0] = make_float2(m0, m1);
                    *(float2*)&vgbuf[e2*VGL + ch0] = make_float2(m2, m3);
                } else if (qc == 0) {
                    red2(out + (size_t)srow[e1]*128 + ch0, m0, m1);
                    red2(out + (size_t)srow[e2]*128 + ch0, m2, m3);
                } else {
                    #pragma unroll
                    for (int h = 0; h < 2; h++) {
                        int e = h ? e2 : e1;
                        float rg0 = h ? m2 : m0;
                        float rg1 = h ? m3 : m1;
                        int row = srow[e], col = scol[e];
                        float2 vg = *(const float2*)&vgbuf[e*VGL + ch0];
                        float u0 = sunit[e*3+0], u1 = sunit[e*3+1], u2 = sunit[e*3+2];
                        float vb0=0.f,vb1=0.f,vb2=0.f,vb3=0.f,vb4=0.f,vb5=0.f;
                        if (type != 1) {
                            const float2* vp = (const float2*)(V + (size_t)col*384 + ch0*3);
                            float2 p0 = vp[0], p1 = vp[1], p2 = vp[2];
                            vb0=p0.x; vb1=p0.y; vb2=p1.x; vb3=p1.y; vb4=p2.x; vb5=p2.y;
                        }
                        float d0 = vb0*vg.x + u0*rg0;
                        float d1 = vb1*vg.x + u1*rg0;
                        float d2 = vb2*vg.x + u2*rg0;
                        float d3 = vb3*vg.y + u0*rg1;
                        float d4 = vb4*vg.y + u1*rg1;
                        float d5 = vb5*vg.y + u2*rg1;
                        float* op = out + HN + (size_t)row*384 + ch0*3;
                        red2(op,     d0, d1);
                        red2(op + 2, d2, d3);
                        red2(op + 4, d4, d5);
                    }
                }
            }
        }
    }
}

/* ---------------- finalize ---------------- */
__global__ void k_fin(float* __restrict__ out,
                      const unsigned char* __restrict__ m2d,
                      const unsigned char* __restrict__ m3d, int total)
{
    int idx = blockIdx.x*256 + threadIdx.x;
    if (idx >= total) return;
    int i = (idx < HN) ? (idx >> 7) : ((idx - HN) / 384);
    float v = out[idx];
    v = fminf(fmaxf(v, -100.f), 100.f);
    bool keep = ((m2d[i] | m3d[i] | g_mask[i]) != 0);
    out[idx] = keep ? v : 0.f;
}

#define SMEM_EDGE ((32*XSL + 32*VGL + 3200 + 3200 + 2*32 + 4*32 + 96 + 32) * sizeof(float))

extern "C" void kernel_launch(void* const* d_in, const int* in_sizes, int n_in,
                              void* d_out, int out_size)
{
    int o = (in_sizes[3] == 1) ? 1 : 0;
    const float* H      = (const float*)d_in[0];
    const float* V      = (const float*)d_in[1];
    const float* Z      = (const float*)d_in[2];
    const float* H2d    = (const float*)d_in[3+o];
    const unsigned char* m2d = (const unsigned char*)d_in[4+o];
    const int*   E2didx = (const int*)d_in[5+o];
    const float* E2dfeat= (const float*)d_in[6+o];
    const float* Z3d    = (const float*)d_in[7+o];
    const unsigned char* m3d = (const unsigned char*)d_in[8+o];
    const int*   Edidx  = (const int*)d_in[9+o];
    const float* Edval  = (const float*)d_in[10+o];
    const float* virt   = (const float*)d_in[11+o];
    const float* ETe    = (const float*)d_in[12+o];
    const float* Wrbf   = (const float*)d_in[13+o];
    const float* We2d   = (const float*)d_in[14+o];
    const float* Wi     = (const float*)d_in[15+o];
    const float* Wphi1  = (const float*)d_in[16+o];
    const float* bphi1  = (const float*)d_in[17+o];
    const float* Wphi2  = (const float*)d_in[18+o];
    const float* bphi2  = (const float*)d_in[19+o];
    const float* Wmsg   = (const float*)d_in[20+o];
    const float* bmsg   = (const float*)d_in[21+o];
    float* out = (float*)d_out;

    cudaMemsetAsync(d_out, 0, (size_t)out_size * sizeof(float));
    k_pre<<<339, 256>>>(Wi, Wphi1, bphi1, We2d, Wrbf, ETe, virt, Wphi2, Wmsg);
    k_maskset<<<782, 256>>>(Edidx);
    k_nproj<<<1250, 128>>>(H, H2d);
    cudaFuncSetAttribute(k_edge, cudaFuncAttributeMaxDynamicSharedMemorySize,
                         (int)SMEM_EDGE);
    k_edge<<<NBT, 128, SMEM_EDGE>>>(E2didx, E2dfeat, Edidx, Edval, Z, Z3d, V,
                                    bphi2, bmsg, out);
    k_fin<<<(HN + 3*HN + 255)/256, 256>>>(out, m2d, m3d, HN + 3*HN);
}

// round 12
// speedup vs baseline: 1.6788x; 1.0903x over previous
#include <cuda_runtime.h>
#include <math.h>

#define NN   20000
#define E1C  100000
#define E2C  100000
#define HN   (NN*128)
#define CUTV 6.0f
#define PI_F 3.14159265358979f
#define XSL  196   /* 32x196 fp32 xs rows */
#define VGL  132   /* vg/rg buffer stride; 132%32=4 -> conflict-light */

#define NB0  3125
#define NB1  625
#define NB2  3125
#define NBT  (NB0+NB1+NB2)

typedef unsigned long long u64t;

/* ---------------- persistent device scratch ---------------- */
__device__ __align__(16) float g_WcT[256*128];
__device__ __align__(16) float g_Wc2dT[64*128];
__device__ __align__(16) float g_WcrbfT[64*128];
__device__ __align__(16) float g_etb[3*128];
__device__ __align__(16) float g_cvec[128];
__device__ __align__(16) float g_nproj[(size_t)2*NN*128];
/* pre-swizzled bf16 B fragments: [qc(3)][kt(12)][ntile(16)][lane(32)] x uint2 */
__device__ __align__(16) uint2 g_WfH[576*32];
__device__ __align__(16) uint2 g_WfL[576*32];
__device__ unsigned char g_mask[NN];

/* -------- packed f32x2 helpers -------- */
__device__ __forceinline__ u64t fma2d(u64t a, u64t b, u64t c) {
    u64t d; asm("fma.rn.f32x2 %0, %1, %2, %3;" : "=l"(d) : "l"(a), "l"(b), "l"(c));
    return d;
}
__device__ __forceinline__ u64t splat2(float x) {
    u64t d; asm("mov.b64 %0, {%1, %1};" : "=l"(d) : "r"(__float_as_uint(x)));
    return d;
}
__device__ __forceinline__ u64t fadd2(u64t a, u64t b) { return fma2d(a, splat2(1.0f), b); }
__device__ __forceinline__ float lo2(u64t d) { return __uint_as_float((unsigned)(d & 0xffffffffull)); }
__device__ __forceinline__ float hi2(u64t d) { return __uint_as_float((unsigned)(d >> 32)); }
__device__ __forceinline__ void red2(float* p, float a, float b) {
    asm volatile("red.global.add.v2.f32 [%0], {%1, %2};" :: "l"(p), "f"(a), "f"(b) : "memory");
}
__device__ __forceinline__ void red4(float* p, float a, float b, float c, float d) {
    asm volatile("red.global.add.v4.f32 [%0], {%1, %2, %3, %4};"
                 :: "l"(p), "f"(a), "f"(b), "f"(c), "f"(d) : "memory");
}
/* bf16x2 pack: low half = x, high half = y; plus hi/lo split */
__device__ __forceinline__ void bfsplit2(float x, float y, unsigned& hi, unsigned& lo) {
    unsigned h; asm("cvt.rn.bf16x2.f32 %0, %1, %2;" : "=r"(h) : "f"(y), "f"(x));
    float xh = __uint_as_float(h << 16);
    float yh = __uint_as_float(h & 0xffff0000u);
    asm("cvt.rn.bf16x2.f32 %0, %1, %2;" : "=r"(lo) : "f"(y - yh), "f"(x - xh));
    hi = h;
}
__device__ __forceinline__ void ldmA(unsigned a[4], unsigned saddr) {
    asm volatile("ldmatrix.sync.aligned.m8n8.x4.shared.b16 {%0,%1,%2,%3}, [%4];"
                 : "=r"(a[0]), "=r"(a[1]), "=r"(a[2]), "=r"(a[3]) : "r"(saddr));
}
__device__ __forceinline__ void mmabf(float* d, const unsigned a[4], uint2 b) {
    asm volatile("mma.sync.aligned.m16n8k16.row.col.f32.bf16.bf16.f32 "
                 "{%0,%1,%2,%3}, {%4,%5,%6,%7}, {%8,%9}, {%0,%1,%2,%3};"
                 : "+f"(d[0]), "+f"(d[1]), "+f"(d[2]), "+f"(d[3])
                 : "r"(a[0]), "r"(a[1]), "r"(a[2]), "r"(a[3]), "r"(b.x), "r"(b.y));
}

/* ---------------- fused precompute ---------------- */
__global__ void k_pre(const float* __restrict__ W_i, const float* __restrict__ W_phi1,
                      const float* __restrict__ b_phi1, const float* __restrict__ W_e2d,
                      const float* __restrict__ W_rbf, const float* __restrict__ ET,
                      const float* __restrict__ virt,
                      const float* __restrict__ W_phi2, const float* __restrict__ W_msg)
{
    int b = blockIdx.x;
    int t = threadIdx.x;
    if (b < 194) {
        int idx = b*256 + t;
        if (idx < NN) g_mask[idx] = 0;
        if (idx < 32768) {
            int k = idx >> 7, p = idx & 127;
            float s = 0.f;
            #pragma unroll 4
            for (int j = 0; j < 128; j++) s += W_phi1[p*288 + j] * W_i[j*256 + k];
            g_WcT[idx] = s;
        } else if (idx < 40960) {
            int i = idx - 32768; int k = i >> 7, p = i & 127;
            float s = 0.f;
            #pragma unroll 4
            for (int j = 0; j < 128; j++) s += W_phi1[p*288 + 128 + j] * W_e2d[j*64 + k];
            g_Wc2dT[i] = s;
        } else if (idx < 49152) {
            int i = idx - 40960; int k = i >> 7, p = i & 127;
            float s = 0.f;
            #pragma unroll 4
            for (int j = 0; j < 128; j++) s += W_phi1[p*288 + 128 + j] * W_rbf[j*64 + k];
            g_WcrbfT[i] = s;
        } else if (idx < 49536) {
            int i = idx - 49152; int tt = i >> 7, p = i & 127;
            float s = b_phi1[p];
            #pragma unroll
            for (int l = 0; l < 32; l++) s += W_phi1[p*288 + 256 + l] * ET[tt*32 + l];
            g_etb[i] = s;
        }
    } else if (b == 194) {
        __shared__ float u[128];
        if (t < 128) {
            float s = 0.f;
            #pragma unroll 4
            for (int j = 0; j < 128; j++) s += W_i[t*256 + 128 + j] * virt[j];
            u[t] = s;
        }
        __syncthreads();
        if (t < 128) {
            float c = 0.f;
            #pragma unroll 4
            for (int q = 0; q < 128; q++) c += W_phi1[t*288 + q] * u[q];
            g_cvec[t] = c;
        }
    } else {
        /* B fragment build: idx over 576 records x 32 lanes x 2 halves */
        int idx = (b - 195)*256 + t;
        if (idx < 36864) {
            int rec  = idx >> 6;
            int wi   = idx & 63;
            int lane = wi >> 1;
            int half = wi & 1;
            int nt = rec & 15;
            int kt = (rec >> 4) % 12;
            int qc = rec / 192;
            int ch = qc*128 + nt*8 + (lane >> 2);
            int k0 = kt*16 + (lane & 3)*2 + half*8;
            float w0, w1;
            if (k0 < 128) {
                w0 = W_phi2[(size_t)ch*128 + k0];
                w1 = W_phi2[(size_t)ch*128 + k0 + 1];
            } else {
                w0 = W_msg[(size_t)ch*64 + k0 - 128];
                w1 = W_msg[(size_t)ch*64 + k0 - 127];
            }
            unsigned hi, lo;
            bfsplit2(w0, w1, hi, lo);
            ((unsigned*)g_WfH)[rec*64 + lane*2 + half] = hi;
            ((unsigned*)g_WfL)[rec*64 + lane*2 + half] = lo;
        }
    }
}

__global__ void k_maskset(const int* __restrict__ Edist_idx)
{
    int idx = blockIdx.x*256 + threadIdx.x;
    if (idx < 2*E2C) g_mask[Edist_idx[idx]] = 1;
}

/* ---------------- node projection ---------------- */
__global__ void __launch_bounds__(128) k_nproj(const float* __restrict__ H,
                                               const float* __restrict__ H2d)
{
    __shared__ float hx[16*128];
    __shared__ float h2[16*128];
    int t = threadIdx.x;
    int i0 = blockIdx.x * 16;
    #pragma unroll
    for (int it = 0; it < 16; it++) {
        int idx = t + it*128;
        int nd = idx >> 7, p = idx & 127;
        hx[idx] = H  [(size_t)(i0+nd)*128 + p];
        h2[idx] = H2d[(size_t)(i0+nd)*128 + p];
    }
    __syncthreads();
    float a1[16], a2[16];
    #pragma unroll
    for (int nd = 0; nd < 16; nd++) { a1[nd] = 0.f; a2[nd] = 0.f; }
    for (int kk = 0; kk < 128; kk += 4) {
        float w0 = g_WcT[(kk+0)*128+t], w1 = g_WcT[(kk+1)*128+t];
        float w2 = g_WcT[(kk+2)*128+t], w3 = g_WcT[(kk+3)*128+t];
        float v0 = g_WcT[(128+kk+0)*128+t], v1 = g_WcT[(128+kk+1)*128+t];
        float v2 = g_WcT[(128+kk+2)*128+t], v3 = g_WcT[(128+kk+3)*128+t];
        #pragma unroll
        for (int nd = 0; nd < 16; nd++) {
            float4 f = *(const float4*)&hx[nd*128 + kk];
            a1[nd] += f.x*w0 + f.y*w1 + f.z*w2 + f.w*w3;
            float4 g = *(const float4*)&h2[nd*128 + kk];
            a2[nd] += g.x*v0 + g.y*v1 + g.z*v2 + g.w*v3;
        }
    }
    float cv = g_cvec[t];
    #pragma unroll
    for (int nd = 0; nd < 16; nd++) {
        g_nproj[(size_t)(i0+nd)*128 + t]    = a1[nd] + a2[nd];
        g_nproj[(size_t)(NN+i0+nd)*128 + t] = a1[nd] + cv;
    }
}

/* ------- fp32 GEMM micro-kernel (phase A only) ------- */
__device__ __forceinline__ void gemm64g(const float* __restrict__ W, int ldw,
                                        const float* __restrict__ xsp,
                                        int c0, int c1, u64t (&acc)[4][4])
{
    #pragma unroll 2
    for (int k4 = 0; k4 < 64; k4 += 4) {
        float4 xv[4];
        #pragma unroll
        for (int j = 0; j < 4; j++)
            xv[j] = *(const float4*)(xsp + j*(4*XSL) + k4);
        #pragma unroll
        for (int kk = 0; kk < 4; kk++) {
            ulonglong2 wA = *(const ulonglong2*)(W + (size_t)(k4+kk)*ldw + c0);
            ulonglong2 wB = *(const ulonglong2*)(W + (size_t)(k4+kk)*ldw + c1);
            #pragma unroll
            for (int j = 0; j < 4; j++) {
                u64t a = splat2(((const float*)&xv[j])[kk]);
                acc[0][j] = fma2d(a, wA.x, acc[0][j]);
                acc[1][j] = fma2d(a, wA.y, acc[1][j]);
                acc[2][j] = fma2d(a, wB.x, acc[2][j]);
                acc[3][j] = fma2d(a, wB.y, acc[3][j]);
            }
        }
    }
}

/* ---------------- fused per-edge kernel: 32 edges / 128 threads ---------------- */
__global__ void __launch_bounds__(128, 3) k_edge(
    const int* __restrict__ E2d_idx, const float* __restrict__ E2d_feat,
    const int* __restrict__ Edist_idx, const float* __restrict__ Edist_val,
    const float* __restrict__ Z, const float* __restrict__ Z3d,
    const float* __restrict__ V,
    const float* __restrict__ b_phi2, const float* __restrict__ b_msg,
    float* __restrict__ out)
{
    extern __shared__ float sm[];
    float*    smxs  = sm;                             /* 32 x 196 fp32 (dead after cvt) */
    float*    rgbuf = sm;                             /* alias: 32 x 132 (used in phase C) */
    unsigned* xshiw = (unsigned*)(sm + 32*XSL);       /* 32 x 100 u32 (bf16x2) */
    unsigned* xslow = xshiw + 3200;                   /* 32 x 100 u32 */
    float*    vgbuf = (float*)(xslow + 3200);         /* 32 x 132 */
    int*   srow  = (int*)(vgbuf + 32*VGL);
    int*   scol  = srow + 32;
    float* sdist = (float*)(scol + 32);
    float* senvd = sdist + 32;
    float* sdval = senvd + 32;
    float* senv2 = sdval + 32;
    float* sunit = senv2 + 32;                        /* 32 x 3 */

    int t  = threadIdx.x;
    int w  = t >> 5;
    int l  = t & 31;
    /* phase A mapping */
    int tp = l & 7;
    int te = l >> 3;
    int cb = (w & 1) * 64;
    int eb = (w >> 1) * 16;
    int c0 = cb + tp*4;
    int c1 = cb + 32 + tp*4;
    int ebte = eb + te;

    int bid = blockIdx.x;
    int base = bid * 32;
    int type = (bid < NB0) ? 0 : (bid < NB0+NB1 ? 1 : 2);

    /* --- metadata + geometry (warp 0) --- */
    if (t < 32) {
        int eg = base + t;
        int row, col; float dval = 0.f;
        if (type == 0)      { row = E2d_idx[eg]; col = E2d_idx[E1C + eg]; }
        else if (type == 1) { int i = eg - E1C; row = i; col = NN + i; }
        else                { int j = eg - E1C - NN; row = Edist_idx[j];
                              col = Edist_idx[E2C + j]; dval = Edist_val[j]; }
        srow[t] = row; scol[t] = col; sdval[t] = dval;
        float zr0 = Z[row*3+0], zr1 = Z[row*3+1], zr2 = Z[row*3+2];
        float zc0, zc1, zc2;
        if (col < NN) { zc0 = Z[col*3+0]; zc1 = Z[col*3+1]; zc2 = Z[col*3+2]; }
        else { int c2 = col - NN; zc0 = Z3d[c2*3+0]; zc1 = Z3d[c2*3+1]; zc2 = Z3d[c2*3+2]; }
        float r0 = zr0-zc0, r1 = zr1-zc1, r2 = zr2-zc2;
        float d = sqrtf(r0*r0 + r1*r1 + r2*r2 + 1e-8f);
        sdist[t] = d;
        float inv = 1.0f / d;
        sunit[t*3+0] = r0*inv; sunit[t*3+1] = r1*inv; sunit[t*3+2] = r2*inv;
        float cl = fminf(d * (1.0f/CUTV), 1.0f);
        senvd[t] = 0.5f * (cosf(PI_F*cl) + 1.0f);
        float cl2 = fminf(fmaxf(dval * (1.0f/CUTV), 0.f), 1.0f);
        senv2[t] = 0.5f * (cosf(PI_F*cl2) + 1.0f);
    }
    __syncthreads();

    /* --- per-edge 64-dim features into xs[e][128..191] --- */
    const float cstep = CUTV / 63.0f;
    const float i2w2  = 1.0f / (2.0f * (CUTV/64.0f) * (CUTV/64.0f));
    if (type == 0) {
        #pragma unroll
        for (int it = 0; it < 16; it++) {
            int idx = t + it*128; int e = idx & 31, k = idx >> 5;
            smxs[e*XSL + 128 + k] = E2d_feat[(size_t)k*E1C + base + e];
        }
    } else if (type == 2) {
        #pragma unroll
        for (int it = 0; it < 16; it++) {
            int idx = t + it*128; int e = idx & 31, k = idx >> 5;
            float diff = sdval[e] - k*cstep;
            smxs[e*XSL + 128 + k] = expf(-diff*diff*i2w2) * senv2[e];
        }
    }
    /* --- gather node projection + edge-type bias --- */
    u64t gn[4][4];
    #pragma unroll
    for (int j = 0; j < 4; j++) {
        const float* np = g_nproj + (size_t)scol[ebte + 4*j]*128;
        ulonglong2 ga = *(const ulonglong2*)(np + c0);
        ulonglong2 gb = *(const ulonglong2*)(np + c1);
        gn[0][j] = ga.x; gn[1][j] = ga.y; gn[2][j] = gb.x; gn[3][j] = gb.y;
    }
    u64t et2[4];
    {
        ulonglong2 ea = *(const ulonglong2*)(g_etb + type*128 + c0);
        ulonglong2 eb2 = *(const ulonglong2*)(g_etb + type*128 + c1);
        et2[0] = ea.x; et2[1] = ea.y; et2[2] = eb2.x; et2[3] = eb2.y;
    }
    __syncthreads();

    /* --- phase A (fp32): act = nproj[col] + etb (+ feats @ Wtype^T); silu --- */
    {
        u64t acc[4][4] = {};
        if (type == 0)
            gemm64g(g_Wc2dT, 128, smxs + ebte*XSL + 128, c0, c1, acc);
        else if (type == 2)
            gemm64g(g_WcrbfT, 128, smxs + ebte*XSL + 128, c0, c1, acc);
        #pragma unroll
        for (int j = 0; j < 4; j++) {
            int e = ebte + 4*j;
            float v[8];
            #pragma unroll
            for (int q = 0; q < 4; q++) {
                u64t s = fadd2(acc[q][j], fadd2(gn[q][j], et2[q]));
                float a = lo2(s), b = hi2(s);
                v[2*q]   = a / (1.0f + expf(-a));
                v[2*q+1] = b / (1.0f + expf(-b));
            }
            *(float4*)&smxs[e*XSL + c0] = make_float4(v[0], v[1], v[2], v[3]);
            *(float4*)&smxs[e*XSL + c1] = make_float4(v[4], v[5], v[6], v[7]);
        }
    }
    __syncthreads();

    /* --- geometric RBF overwrites feats --- */
    #pragma unroll
    for (int it = 0; it < 16; it++) {
        int idx = t + it*128; int e = idx & 31, k = idx >> 5;
        float diff = sdist[e] - k*cstep;
        smxs[e*XSL + 128 + k] = expf(-diff*diff*i2w2) * senvd[e];
    }
    __syncthreads();

    /* --- convert xs fp32 -> bf16 hi/lo (rows padded to 200 bf16 = 400B) --- */
    #pragma unroll
    for (int it = 0; it < 24; it++) {
        int lin = t + it*128;          /* 0..3071 */
        int e  = lin / 96;
        int kp = lin % 96;
        float2 v = *(const float2*)&smxs[e*XSL + kp*2];
        unsigned hi, lo;
        bfsplit2(v.x, v.y, hi, lo);
        xshiw[e*100 + kp] = hi;
        xslow[e*100 + kp] = lo;
    }
    __syncthreads();   /* smxs now dead -> rgbuf alias is safe */

    /* --- phase C: bf16x3 tensor-core GEMM; qc order {1,2,0} --- */
    unsigned xshi_s = (unsigned)__cvta_generic_to_shared(xshiw);
    unsigned xslo_s = (unsigned)__cvta_generic_to_shared(xslow);
    unsigned a_off  = (unsigned)((l & 15)*400 + (l >> 4)*16);

    #pragma unroll 1
    for (int qi = 0; qi < 3; qi++) {
        int qc = (qi == 0) ? 1 : (qi == 1 ? 2 : 0);
        float accP[2][4][4], accW[2][4][4];
        #pragma unroll
        for (int mt = 0; mt < 2; mt++)
            #pragma unroll
            for (int nt = 0; nt < 4; nt++)
                #pragma unroll
                for (int r = 0; r < 4; r++) { accP[mt][nt][r] = 0.f; accW[mt][nt][r] = 0.f; }

        #pragma unroll 1
        for (int pass = 0; pass < 3; pass++) {
            unsigned As = (pass == 2) ? xslo_s : xshi_s;
            const uint2* Wf = ((pass == 1) ? g_WfL : g_WfH) + l;
            int recb = (qc*12)*16 + (w << 2);
            #pragma unroll
            for (int kt = 0; kt < 12; kt++) {
                unsigned a0[4], a1[4];
                ldmA(a0, As + a_off + kt*32);
                ldmA(a1, As + a_off + kt*32 + 6400);
                #pragma unroll
                for (int nt = 0; nt < 4; nt++) {
                    uint2 bfr = Wf[(size_t)(recb + kt*16 + nt)*32];
                    if (kt < 8) { mmabf(accP[0][nt], a0, bfr); mmabf(accP[1][nt], a1, bfr); }
                    else        { mmabf(accW[0][nt], a0, bfr); mmabf(accW[1][nt], a1, bfr); }
                }
            }
        }

        /* epilogue */
        #pragma unroll
        for (int nt = 0; nt < 4; nt++) {
            int ch0 = (w << 5) + (nt << 3) + ((l & 3) << 1);
            float2 bp = *(const float2*)&b_phi2[qc*128 + ch0];
            float2 bm = *(const float2*)&b_msg [qc*128 + ch0];
            #pragma unroll
            for (int mt = 0; mt < 2; mt++) {
                float m0 = (accP[mt][nt][0] + bp.x) * (accW[mt][nt][0] + bm.x);
                float m1 = (accP[mt][nt][1] + bp.y) * (accW[mt][nt][1] + bm.y);
                float m2 = (accP[mt][nt][2] + bp.x) * (accW[mt][nt][2] + bm.x);
                float m3 = (accP[mt][nt][3] + bp.y) * (accW[mt][nt][3] + bm.y);
                int e1 = (mt << 4) + (l >> 2);
                int e2 = e1 + 8;
                if (qc == 1) {
                    *(float2*)&vgbuf[e1*VGL + ch0] = make_float2(m0, m1);
                    *(float2*)&vgbuf[e2*VGL + ch0] = make_float2(m2, m3);
                } else if (qc == 2) {
                    *(float2*)&rgbuf[e1*VGL + ch0] = make_float2(m0, m1);
                    *(float2*)&rgbuf[e2*VGL + ch0] = make_float2(m2, m3);
                } else { /* qc == 0 : H scatter (already sector-optimal) */
                    red2(out + (size_t)srow[e1]*128 + ch0, m0, m1);
                    red2(out + (size_t)srow[e2]*128 + ch0, m2, m3);
                }
            }
        }
    }

    /* --- cooperative V pass: coalesced gather + red4 scatter --- */
    __syncthreads();
    {
        int e   = t >> 2;
        int seg = t & 3;
        int row = srow[e], col = scol[e];
        float u0 = sunit[e*3+0], u1 = sunit[e*3+1], u2 = sunit[e*3+2];
        int r0 = seg % 3;                 /* (4*seg) % 3 */
        float ua = (r0==0) ? u0 : ((r0==1) ? u1 : u2);   /* u[r]     */
        float ub = (r0==0) ? u1 : ((r0==1) ? u2 : u0);   /* u[(r+1)%3] */
        float uc = (r0==0) ? u2 : ((r0==1) ? u0 : u1);   /* u[(r+2)%3] */
        const float* vrow = V + (size_t)col*384;
        float* op = out + HN + (size_t)row*384;
        const float* vgr = vgbuf + e*VGL;
        const float* rgr = rgbuf + e*VGL;
        int ch = (seg == 3) ? 4 : seg;    /* (4*seg)/3 */
        int r  = r0;
        #pragma unroll
        for (int i = 0; i < 24; i++) {
            int fo = 4*seg + 16*i;
            float4 vb;
            if (type != 1) vb = *(const float4*)(vrow + fo);
            else           vb = make_float4(0.f, 0.f, 0.f, 0.f);
            float vga = vgr[ch], vgb2 = vgr[ch+1];
            float rga = rgr[ch], rgb2 = rgr[ch+1];
            float uA, uB, uC;
            if (i % 3 == 0)      { uA = ua; uB = ub; uC = uc; }
            else if (i % 3 == 1) { uA = ub; uB = uc; uC = ua; }
            else                 { uA = uc; uB = ua; uC = ub; }
            bool cB = (r == 2);
            bool cC = (r >= 1);
            float vg1 = cB ? vgb2 : vga, rg1 = cB ? rgb2 : rga;
            float vg2 = cC ? vgb2 : vga, rg2 = cC ? rgb2 : rga;
            float dx = vb.x*vga + uA*rga;
            float dy = vb.y*vg1 + uB*rg1;
            float dz = vb.z*vg2 + uC*rg2;
            float dw = vb.w*vgb2 + uA*rgb2;
            red4(op + fo, dx, dy, dz, dw);
            ch += (r == 2) ? 6 : 5;
            r   = (r == 2) ? 0 : r + 1;
        }
    }
}

/* ---------------- finalize ---------------- */
__global__ void k_fin(float* __restrict__ out,
                      const unsigned char* __restrict__ m2d,
                      const unsigned char* __restrict__ m3d, int total)
{
    int idx = blockIdx.x*256 + threadIdx.x;
    if (idx >= total) return;
    int i = (idx < HN) ? (idx >> 7) : ((idx - HN) / 384);
    float v = out[idx];
    v = fminf(fmaxf(v, -100.f), 100.f);
    bool keep = ((m2d[i] | m3d[i] | g_mask[i]) != 0);
    out[idx] = keep ? v : 0.f;
}

#define SMEM_EDGE ((32*XSL + 3200 + 3200 + 32*VGL + 2*32 + 4*32 + 96 + 32) * sizeof(float))

extern "C" void kernel_launch(void* const* d_in, const int* in_sizes, int n_in,
                              void* d_out, int out_size)
{
    int o = (in_sizes[3] == 1) ? 1 : 0;
    const float* H      = (const float*)d_in[0];
    const float* V      = (const float*)d_in[1];
    const float* Z      = (const float*)d_in[2];
    const float* H2d    = (const float*)d_in[3+o];
    const unsigned char* m2d = (const unsigned char*)d_in[4+o];
    const int*   E2didx = (const int*)d_in[5+o];
    const float* E2dfeat= (const float*)d_in[6+o];
    const float* Z3d    = (const float*)d_in[7+o];
    const unsigned char* m3d = (const unsigned char*)d_in[8+o];
    const int*   Edidx  = (const int*)d_in[9+o];
    const float* Edval  = (const float*)d_in[10+o];
    const float* virt   = (const float*)d_in[11+o];
    const float* ETe    = (const float*)d_in[12+o];
    const float* Wrbf   = (const float*)d_in[13+o];
    const float* We2d   = (const float*)d_in[14+o];
    const float* Wi     = (const float*)d_in[15+o];
    const float* Wphi1  = (const float*)d_in[16+o];
    const float* bphi1  = (const float*)d_in[17+o];
    const float* Wphi2  = (const float*)d_in[18+o];
    const float* bphi2  = (const float*)d_in[19+o];
    const float* Wmsg   = (const float*)d_in[20+o];
    const float* bmsg   = (const float*)d_in[21+o];
    float* out = (float*)d_out;

    cudaMemsetAsync(d_out, 0, (size_t)out_size * sizeof(float));
    k_pre<<<339, 256>>>(Wi, Wphi1, bphi1, We2d, Wrbf, ETe, virt, Wphi2, Wmsg);
    k_maskset<<<782, 256>>>(Edidx);
    k_nproj<<<1250, 128>>>(H, H2d);
    cudaFuncSetAttribute(k_edge, cudaFuncAttributeMaxDynamicSharedMemorySize,
                         (int)SMEM_EDGE);
    k_edge<<<NBT, 128, SMEM_EDGE>>>(E2didx, E2dfeat, Edidx, Edval, Z, Z3d, V,
                                    bphi2, bmsg, out);
    k_fin<<<(HN + 3*HN + 255)/256, 256>>>(out, m2d, m3d, HN + 3*HN);
}

// round 13
// speedup vs baseline: 1.6947x; 1.0094x over previous
#include <cuda_runtime.h>
#include <math.h>

#define NN   20000
#define E1C  100000
#define E2C  100000
#define HN   (NN*128)
#define CUTV 6.0f
#define PI_F 3.14159265358979f
#define XSL  196   /* 32x196 fp32 xs rows */
#define VGL  132   /* vg/rg buffer stride; 132%32=4 -> conflict-light */

#define NB0  3125
#define NB1  625
#define NB2  3125
#define NBT  (NB0+NB1+NB2)

typedef unsigned long long u64t;

/* ---------------- persistent device scratch ---------------- */
__device__ __align__(16) float g_WcT[256*128];
__device__ __align__(16) float g_Wc2dT[64*128];
__device__ __align__(16) float g_WcrbfT[64*128];
__device__ __align__(16) float g_etb[3*128];
__device__ __align__(16) float g_cvec[128];
__device__ __align__(16) float g_nproj[(size_t)2*NN*128];
/* pre-swizzled bf16 B fragments: [qc(3)][kt(12)][ntile(16)][lane(32)] x uint2 */
__device__ __align__(16) uint2 g_WfH[576*32];
__device__ __align__(16) uint2 g_WfL[576*32];
__device__ unsigned char g_mask[NN];

/* -------- packed f32x2 helpers -------- */
__device__ __forceinline__ u64t fma2d(u64t a, u64t b, u64t c) {
    u64t d; asm("fma.rn.f32x2 %0, %1, %2, %3;" : "=l"(d) : "l"(a), "l"(b), "l"(c));
    return d;
}
__device__ __forceinline__ u64t splat2(float x) {
    u64t d; asm("mov.b64 %0, {%1, %1};" : "=l"(d) : "r"(__float_as_uint(x)));
    return d;
}
__device__ __forceinline__ u64t fadd2(u64t a, u64t b) { return fma2d(a, splat2(1.0f), b); }
__device__ __forceinline__ float lo2(u64t d) { return __uint_as_float((unsigned)(d & 0xffffffffull)); }
__device__ __forceinline__ float hi2(u64t d) { return __uint_as_float((unsigned)(d >> 32)); }
__device__ __forceinline__ void red2(float* p, float a, float b) {
    asm volatile("red.global.add.v2.f32 [%0], {%1, %2};" :: "l"(p), "f"(a), "f"(b) : "memory");
}
__device__ __forceinline__ void red4(float* p, float a, float b, float c, float d) {
    asm volatile("red.global.add.v4.f32 [%0], {%1, %2, %3, %4};"
                 :: "l"(p), "f"(a), "f"(b), "f"(c), "f"(d) : "memory");
}
/* bf16x2 pack: low half = x, high half = y; plus hi/lo split */
__device__ __forceinline__ void bfsplit2(float x, float y, unsigned& hi, unsigned& lo) {
    unsigned h; asm("cvt.rn.bf16x2.f32 %0, %1, %2;" : "=r"(h) : "f"(y), "f"(x));
    float xh = __uint_as_float(h << 16);
    float yh = __uint_as_float(h & 0xffff0000u);
    asm("cvt.rn.bf16x2.f32 %0, %1, %2;" : "=r"(lo) : "f"(y - yh), "f"(x - xh));
    hi = h;
}
__device__ __forceinline__ void ldmA(unsigned a[4], unsigned saddr) {
    asm volatile("ldmatrix.sync.aligned.m8n8.x4.shared.b16 {%0,%1,%2,%3}, [%4];"
                 : "=r"(a[0]), "=r"(a[1]), "=r"(a[2]), "=r"(a[3]) : "r"(saddr));
}
__device__ __forceinline__ void mmabf(float* d, const unsigned a[4], uint2 b) {
    asm volatile("mma.sync.aligned.m16n8k16.row.col.f32.bf16.bf16.f32 "
                 "{%0,%1,%2,%3}, {%4,%5,%6,%7}, {%8,%9}, {%0,%1,%2,%3};"
                 : "+f"(d[0]), "+f"(d[1]), "+f"(d[2]), "+f"(d[3])
                 : "r"(a[0]), "r"(a[1]), "r"(a[2]), "r"(a[3]), "r"(b.x), "r"(b.y));
}

/* ---------------- fused precompute ---------------- */
__global__ void k_pre(const float* __restrict__ W_i, const float* __restrict__ W_phi1,
                      const float* __restrict__ b_phi1, const float* __restrict__ W_e2d,
                      const float* __restrict__ W_rbf, const float* __restrict__ ET,
                      const float* __restrict__ virt,
                      const float* __restrict__ W_phi2, const float* __restrict__ W_msg)
{
    int b = blockIdx.x;
    int t = threadIdx.x;
    if (b < 194) {
        int idx = b*256 + t;
        if (idx < NN) g_mask[idx] = 0;
        if (idx < 32768) {
            int k = idx >> 7, p = idx & 127;
            float s = 0.f;
            #pragma unroll 4
            for (int j = 0; j < 128; j++) s += W_phi1[p*288 + j] * W_i[j*256 + k];
            g_WcT[idx] = s;
        } else if (idx < 40960) {
            int i = idx - 32768; int k = i >> 7, p = i & 127;
            float s = 0.f;
            #pragma unroll 4
            for (int j = 0; j < 128; j++) s += W_phi1[p*288 + 128 + j] * W_e2d[j*64 + k];
            g_Wc2dT[i] = s;
        } else if (idx < 49152) {
            int i = idx - 40960; int k = i >> 7, p = i & 127;
            float s = 0.f;
            #pragma unroll 4
            for (int j = 0; j < 128; j++) s += W_phi1[p*288 + 128 + j] * W_rbf[j*64 + k];
            g_WcrbfT[i] = s;
        } else if (idx < 49536) {
            int i = idx - 49152; int tt = i >> 7, p = i & 127;
            float s = b_phi1[p];
            #pragma unroll
            for (int l = 0; l < 32; l++) s += W_phi1[p*288 + 256 + l] * ET[tt*32 + l];
            g_etb[i] = s;
        }
    } else if (b == 194) {
        __shared__ float u[128];
        if (t < 128) {
            float s = 0.f;
            #pragma unroll 4
            for (int j = 0; j < 128; j++) s += W_i[t*256 + 128 + j] * virt[j];
            u[t] = s;
        }
        __syncthreads();
        if (t < 128) {
            float c = 0.f;
            #pragma unroll 4
            for (int q = 0; q < 128; q++) c += W_phi1[t*288 + q] * u[q];
            g_cvec[t] = c;
        }
    } else {
        /* B fragment build: idx over 576 records x 32 lanes x 2 halves */
        int idx = (b - 195)*256 + t;
        if (idx < 36864) {
            int rec  = idx >> 6;
            int wi   = idx & 63;
            int lane = wi >> 1;
            int half = wi & 1;
            int nt = rec & 15;
            int kt = (rec >> 4) % 12;
            int qc = rec / 192;
            int ch = qc*128 + nt*8 + (lane >> 2);
            int k0 = kt*16 + (lane & 3)*2 + half*8;
            float w0, w1;
            if (k0 < 128) {
                w0 = W_phi2[(size_t)ch*128 + k0];
                w1 = W_phi2[(size_t)ch*128 + k0 + 1];
            } else {
                w0 = W_msg[(size_t)ch*64 + k0 - 128];
                w1 = W_msg[(size_t)ch*64 + k0 - 127];
            }
            unsigned hi, lo;
            bfsplit2(w0, w1, hi, lo);
            ((unsigned*)g_WfH)[rec*64 + lane*2 + half] = hi;
            ((unsigned*)g_WfL)[rec*64 + lane*2 + half] = lo;
        }
    }
}

__global__ void k_maskset(const int* __restrict__ Edist_idx)
{
    int idx = blockIdx.x*256 + threadIdx.x;
    if (idx < 2*E2C) g_mask[Edist_idx[idx]] = 1;
}

/* ---------------- node projection ---------------- */
__global__ void __launch_bounds__(128) k_nproj(const float* __restrict__ H,
                                               const float* __restrict__ H2d)
{
    __shared__ float hx[16*128];
    __shared__ float h2[16*128];
    int t = threadIdx.x;
    int i0 = blockIdx.x * 16;
    #pragma unroll
    for (int it = 0; it < 16; it++) {
        int idx = t + it*128;
        int nd = idx >> 7, p = idx & 127;
        hx[idx] = H  [(size_t)(i0+nd)*128 + p];
        h2[idx] = H2d[(size_t)(i0+nd)*128 + p];
    }
    __syncthreads();
    float a1[16], a2[16];
    #pragma unroll
    for (int nd = 0; nd < 16; nd++) { a1[nd] = 0.f; a2[nd] = 0.f; }
    for (int kk = 0; kk < 128; kk += 4) {
        float w0 = g_WcT[(kk+0)*128+t], w1 = g_WcT[(kk+1)*128+t];
        float w2 = g_WcT[(kk+2)*128+t], w3 = g_WcT[(kk+3)*128+t];
        float v0 = g_WcT[(128+kk+0)*128+t], v1 = g_WcT[(128+kk+1)*128+t];
        float v2 = g_WcT[(128+kk+2)*128+t], v3 = g_WcT[(128+kk+3)*128+t];
        #pragma unroll
        for (int nd = 0; nd < 16; nd++) {
            float4 f = *(const float4*)&hx[nd*128 + kk];
            a1[nd] += f.x*w0 + f.y*w1 + f.z*w2 + f.w*w3;
            float4 g = *(const float4*)&h2[nd*128 + kk];
            a2[nd] += g.x*v0 + g.y*v1 + g.z*v2 + g.w*v3;
        }
    }
    float cv = g_cvec[t];
    #pragma unroll
    for (int nd = 0; nd < 16; nd++) {
        g_nproj[(size_t)(i0+nd)*128 + t]    = a1[nd] + a2[nd];
        g_nproj[(size_t)(NN+i0+nd)*128 + t] = a1[nd] + cv;
    }
}

/* ------- fp32 GEMM micro-kernel (phase A only) ------- */
__device__ __forceinline__ void gemm64g(const float* __restrict__ W, int ldw,
                                        const float* __restrict__ xsp,
                                        int c0, int c1, u64t (&acc)[4][4])
{
    #pragma unroll 2
    for (int k4 = 0; k4 < 64; k4 += 4) {
        float4 xv[4];
        #pragma unroll
        for (int j = 0; j < 4; j++)
            xv[j] = *(const float4*)(xsp + j*(4*XSL) + k4);
        #pragma unroll
        for (int kk = 0; kk < 4; kk++) {
            ulonglong2 wA = *(const ulonglong2*)(W + (size_t)(k4+kk)*ldw + c0);
            ulonglong2 wB = *(const ulonglong2*)(W + (size_t)(k4+kk)*ldw + c1);
            #pragma unroll
            for (int j = 0; j < 4; j++) {
                u64t a = splat2(((const float*)&xv[j])[kk]);
                acc[0][j] = fma2d(a, wA.x, acc[0][j]);
                acc[1][j] = fma2d(a, wA.y, acc[1][j]);
                acc[2][j] = fma2d(a, wB.x, acc[2][j]);
                acc[3][j] = fma2d(a, wB.y, acc[3][j]);
            }
        }
    }
}

/* ---------------- fused per-edge kernel: 32 edges / 128 threads ---------------- */
__global__ void __launch_bounds__(128, 3) k_edge(
    const int* __restrict__ E2d_idx, const float* __restrict__ E2d_feat,
    const int* __restrict__ Edist_idx, const float* __restrict__ Edist_val,
    const float* __restrict__ Z, const float* __restrict__ Z3d,
    const float* __restrict__ V,
    const float* __restrict__ b_phi2, const float* __restrict__ b_msg,
    float* __restrict__ out)
{
    extern __shared__ float sm[];
    float*    smxs  = sm;                             /* 32 x 196 fp32 (dead after cvt) */
    float*    rgbuf = sm;                             /* alias: 32 x 132 (used in phase C) */
    unsigned* xshiw = (unsigned*)(sm + 32*XSL);       /* 32 x 100 u32 (bf16x2) */
    unsigned* xslow = xshiw + 3200;                   /* 32 x 100 u32 */
    float*    vgbuf = (float*)(xslow + 3200);         /* 32 x 132 */
    int*   srow  = (int*)(vgbuf + 32*VGL);
    int*   scol  = srow + 32;
    float* sdist = (float*)(scol + 32);
    float* senvd = sdist + 32;
    float* sdval = senvd + 32;
    float* senv2 = sdval + 32;
    float* sunit = senv2 + 32;                        /* 32 x 3 */

    int t  = threadIdx.x;
    int w  = t >> 5;
    int l  = t & 31;
    /* phase A mapping */
    int tp = l & 7;
    int te = l >> 3;
    int cb = (w & 1) * 64;
    int eb = (w >> 1) * 16;
    int c0 = cb + tp*4;
    int c1 = cb + 32 + tp*4;
    int ebte = eb + te;

    int bid = blockIdx.x;
    int base = bid * 32;
    int type = (bid < NB0) ? 0 : (bid < NB0+NB1 ? 1 : 2);

    /* --- metadata + geometry (warp 0) --- */
    if (t < 32) {
        int eg = base + t;
        int row, col; float dval = 0.f;
        if (type == 0)      { row = E2d_idx[eg]; col = E2d_idx[E1C + eg]; }
        else if (type == 1) { int i = eg - E1C; row = i; col = NN + i; }
        else                { int j = eg - E1C - NN; row = Edist_idx[j];
                              col = Edist_idx[E2C + j]; dval = Edist_val[j]; }
        srow[t] = row; scol[t] = col; sdval[t] = dval;
        float zr0 = Z[row*3+0], zr1 = Z[row*3+1], zr2 = Z[row*3+2];
        float zc0, zc1, zc2;
        if (col < NN) { zc0 = Z[col*3+0]; zc1 = Z[col*3+1]; zc2 = Z[col*3+2]; }
        else { int c2 = col - NN; zc0 = Z3d[c2*3+0]; zc1 = Z3d[c2*3+1]; zc2 = Z3d[c2*3+2]; }
        float r0 = zr0-zc0, r1 = zr1-zc1, r2 = zr2-zc2;
        float d = sqrtf(r0*r0 + r1*r1 + r2*r2 + 1e-8f);
        sdist[t] = d;
        float inv = 1.0f / d;
        sunit[t*3+0] = r0*inv; sunit[t*3+1] = r1*inv; sunit[t*3+2] = r2*inv;
        float cl = fminf(d * (1.0f/CUTV), 1.0f);
        senvd[t] = 0.5f * (cosf(PI_F*cl) + 1.0f);
        float cl2 = fminf(fmaxf(dval * (1.0f/CUTV), 0.f), 1.0f);
        senv2[t] = 0.5f * (cosf(PI_F*cl2) + 1.0f);
    }
    __syncthreads();

    /* --- per-edge 64-dim features into xs[e][128..191] --- */
    const float cstep = CUTV / 63.0f;
    const float i2w2  = 1.0f / (2.0f * (CUTV/64.0f) * (CUTV/64.0f));
    if (type == 0) {
        #pragma unroll
        for (int it = 0; it < 16; it++) {
            int idx = t + it*128; int e = idx & 31, k = idx >> 5;
            smxs[e*XSL + 128 + k] = E2d_feat[(size_t)k*E1C + base + e];
        }
    } else if (type == 2) {
        #pragma unroll
        for (int it = 0; it < 16; it++) {
            int idx = t + it*128; int e = idx & 31, k = idx >> 5;
            float diff = sdval[e] - k*cstep;
            smxs[e*XSL + 128 + k] = expf(-diff*diff*i2w2) * senv2[e];
        }
    }
    /* --- gather node projection + edge-type bias --- */
    u64t gn[4][4];
    #pragma unroll
    for (int j = 0; j < 4; j++) {
        const float* np = g_nproj + (size_t)scol[ebte + 4*j]*128;
        ulonglong2 ga = *(const ulonglong2*)(np + c0);
        ulonglong2 gb = *(const ulonglong2*)(np + c1);
        gn[0][j] = ga.x; gn[1][j] = ga.y; gn[2][j] = gb.x; gn[3][j] = gb.y;
    }
    u64t et2[4];
    {
        ulonglong2 ea = *(const ulonglong2*)(g_etb + type*128 + c0);
        ulonglong2 eb2 = *(const ulonglong2*)(g_etb + type*128 + c1);
        et2[0] = ea.x; et2[1] = ea.y; et2[2] = eb2.x; et2[3] = eb2.y;
    }
    __syncthreads();

    /* --- phase A (fp32): act = nproj[col] + etb (+ feats @ Wtype^T); silu --- */
    {
        u64t acc[4][4] = {};
        if (type == 0)
            gemm64g(g_Wc2dT, 128, smxs + ebte*XSL + 128, c0, c1, acc);
        else if (type == 2)
            gemm64g(g_WcrbfT, 128, smxs + ebte*XSL + 128, c0, c1, acc);
        #pragma unroll
        for (int j = 0; j < 4; j++) {
            int e = ebte + 4*j;
            float v[8];
            #pragma unroll
            for (int q = 0; q < 4; q++) {
                u64t s = fadd2(acc[q][j], fadd2(gn[q][j], et2[q]));
                float a = lo2(s), b = hi2(s);
                v[2*q]   = a / (1.0f + expf(-a));
                v[2*q+1] = b / (1.0f + expf(-b));
            }
            *(float4*)&smxs[e*XSL + c0] = make_float4(v[0], v[1], v[2], v[3]);
            *(float4*)&smxs[e*XSL + c1] = make_float4(v[4], v[5], v[6], v[7]);
        }
    }
    __syncthreads();

    /* --- geometric RBF overwrites feats --- */
    #pragma unroll
    for (int it = 0; it < 16; it++) {
        int idx = t + it*128; int e = idx & 31, k = idx >> 5;
        float diff = sdist[e] - k*cstep;
        smxs[e*XSL + 128 + k] = expf(-diff*diff*i2w2) * senvd[e];
    }
    __syncthreads();

    /* --- convert xs fp32 -> bf16 hi/lo (rows padded to 200 bf16 = 400B) --- */
    #pragma unroll
    for (int it = 0; it < 24; it++) {
        int lin = t + it*128;          /* 0..3071 */
        int e  = lin / 96;
        int kp = lin % 96;
        float2 v = *(const float2*)&smxs[e*XSL + kp*2];
        unsigned hi, lo;
        bfsplit2(v.x, v.y, hi, lo);
        xshiw[e*100 + kp] = hi;
        xslow[e*100 + kp] = lo;
    }
    __syncthreads();   /* smxs now dead -> rgbuf alias is safe */

    /* --- phase C: kt-major bf16x3 tensor GEMM; qc order {1,2,0} --- */
    unsigned xshi_s = (unsigned)__cvta_generic_to_shared(xshiw);
    unsigned xslo_s = (unsigned)__cvta_generic_to_shared(xslow);
    unsigned a_off  = (unsigned)((l & 15)*400 + (l >> 4)*16);

    #pragma unroll 1
    for (int qi = 0; qi < 3; qi++) {
        int qc = (qi == 0) ? 1 : (qi == 1 ? 2 : 0);
        float accP[2][4][4], accW[2][4][4];
        #pragma unroll
        for (int mt = 0; mt < 2; mt++)
            #pragma unroll
            for (int nt = 0; nt < 4; nt++)
                #pragma unroll
                for (int r = 0; r < 4; r++) { accP[mt][nt][r] = 0.f; accW[mt][nt][r] = 0.f; }

        const uint2* WH = g_WfH + l;
        const uint2* WL = g_WfL + l;
        int recb = (qc*12)*16 + (w << 2);

        #pragma unroll 2
        for (int kt = 0; kt < 8; kt++) {          /* accP: k 0..127 */
            unsigned ah0[4], ah1[4], al0[4], al1[4];
            ldmA(ah0, xshi_s + a_off + kt*32);
            ldmA(ah1, xshi_s + a_off + kt*32 + 6400);
            ldmA(al0, xslo_s + a_off + kt*32);
            ldmA(al1, xslo_s + a_off + kt*32 + 6400);
            #pragma unroll
            for (int nt = 0; nt < 4; nt++) {
                size_t ro = (size_t)(recb + kt*16 + nt)*32;
                uint2 bH = WH[ro];
                uint2 bL = WL[ro];
                mmabf(accP[0][nt], ah0, bH);
                mmabf(accP[1][nt], ah1, bH);
                mmabf(accP[0][nt], ah0, bL);
                mmabf(accP[1][nt], ah1, bL);
                mmabf(accP[0][nt], al0, bH);
                mmabf(accP[1][nt], al1, bH);
            }
        }
        #pragma unroll 2
        for (int kt = 8; kt < 12; kt++) {         /* accW: k 128..191 */
            unsigned ah0[4], ah1[4], al0[4], al1[4];
            ldmA(ah0, xshi_s + a_off + kt*32);
            ldmA(ah1, xshi_s + a_off + kt*32 + 6400);
            ldmA(al0, xslo_s + a_off + kt*32);
            ldmA(al1, xslo_s + a_off + kt*32 + 6400);
            #pragma unroll
            for (int nt = 0; nt < 4; nt++) {
                size_t ro = (size_t)(recb + kt*16 + nt)*32;
                uint2 bH = WH[ro];
                uint2 bL = WL[ro];
                mmabf(accW[0][nt], ah0, bH);
                mmabf(accW[1][nt], ah1, bH);
                mmabf(accW[0][nt], ah0, bL);
                mmabf(accW[1][nt], ah1, bL);
                mmabf(accW[0][nt], al0, bH);
                mmabf(accW[1][nt], al1, bH);
            }
        }

        /* epilogue */
        #pragma unroll
        for (int nt = 0; nt < 4; nt++) {
            int ch0 = (w << 5) + (nt << 3) + ((l & 3) << 1);
            float2 bp = *(const float2*)&b_phi2[qc*128 + ch0];
            float2 bm = *(const float2*)&b_msg [qc*128 + ch0];
            #pragma unroll
            for (int mt = 0; mt < 2; mt++) {
                float m0 = (accP[mt][nt][0] + bp.x) * (accW[mt][nt][0] + bm.x);
                float m1 = (accP[mt][nt][1] + bp.y) * (accW[mt][nt][1] + bm.y);
                float m2 = (accP[mt][nt][2] + bp.x) * (accW[mt][nt][2] + bm.x);
                float m3 = (accP[mt][nt][3] + bp.y) * (accW[mt][nt][3] + bm.y);
                int e1 = (mt << 4) + (l >> 2);
                int e2 = e1 + 8;
                if (qc == 1) {
                    *(float2*)&vgbuf[e1*VGL + ch0] = make_float2(m0, m1);
                    *(float2*)&vgbuf[e2*VGL + ch0] = make_float2(m2, m3);
                } else if (qc == 2) {
                    *(float2*)&rgbuf[e1*VGL + ch0] = make_float2(m0, m1);
                    *(float2*)&rgbuf[e2*VGL + ch0] = make_float2(m2, m3);
                } else { /* qc == 0 : H scatter (sector-optimal) */
                    red2(out + (size_t)srow[e1]*128 + ch0, m0, m1);
                    red2(out + (size_t)srow[e2]*128 + ch0, m2, m3);
                }
            }
        }
    }

    /* --- cooperative V pass: coalesced gather + red4 scatter --- */
    __syncthreads();
    {
        int e   = t >> 2;
        int seg = t & 3;
        int row = srow[e], col = scol[e];
        float u0 = sunit[e*3+0], u1 = sunit[e*3+1], u2 = sunit[e*3+2];
        int r0 = seg % 3;
        float ua = (r0==0) ? u0 : ((r0==1) ? u1 : u2);
        float ub = (r0==0) ? u1 : ((r0==1) ? u2 : u0);
        float uc = (r0==0) ? u2 : ((r0==1) ? u0 : u1);
        const float* vrow = V + (size_t)col*384;
        float* op = out + HN + (size_t)row*384;
        const float* vgr = vgbuf + e*VGL;
        const float* rgr = rgbuf + e*VGL;
        int ch = (seg == 3) ? 4 : seg;
        int r  = r0;
        #pragma unroll
        for (int i = 0; i < 24; i++) {
            int fo = 4*seg + 16*i;
            float4 vb;
            if (type != 1) vb = *(const float4*)(vrow + fo);
            else           vb = make_float4(0.f, 0.f, 0.f, 0.f);
            float vga = vgr[ch], vgb2 = vgr[ch+1];
            float rga = rgr[ch], rgb2 = rgr[ch+1];
            float uA, uB, uC;
            if (i % 3 == 0)      { uA = ua; uB = ub; uC = uc; }
            else if (i % 3 == 1) { uA = ub; uB = uc; uC = ua; }
            else                 { uA = uc; uB = ua; uC = ub; }
            bool cB = (r == 2);
            bool cC = (r >= 1);
            float vg1 = cB ? vgb2 : vga, rg1 = cB ? rgb2 : rga;
            float vg2 = cC ? vgb2 : vga, rg2 = cC ? rgb2 : rga;
            float dx = vb.x*vga + uA*rga;
            float dy = vb.y*vg1 + uB*rg1;
            float dz = vb.z*vg2 + uC*rg2;
            float dw = vb.w*vgb2 + uA*rgb2;
            red4(op + fo, dx, dy, dz, dw);
            ch += (r == 2) ? 6 : 5;
            r   = (r == 2) ? 0 : r + 1;
        }
    }
}

/* ---------------- finalize ---------------- */
__global__ void k_fin(float* __restrict__ out,
                      const unsigned char* __restrict__ m2d,
                      const unsigned char* __restrict__ m3d, int total)
{
    int idx = blockIdx.x*256 + threadIdx.x;
    if (idx >= total) return;
    int i = (idx < HN) ? (idx >> 7) : ((idx - HN) / 384);
    float v = out[idx];
    v = fminf(fmaxf(v, -100.f), 100.f);
    bool keep = ((m2d[i] | m3d[i] | g_mask[i]) != 0);
    out[idx] = keep ? v : 0.f;
}

#define SMEM_EDGE ((32*XSL + 3200 + 3200 + 32*VGL + 2*32 + 4*32 + 96 + 32) * sizeof(float))

extern "C" void kernel_launch(void* const* d_in, const int* in_sizes, int n_in,
                              void* d_out, int out_size)
{
    int o = (in_sizes[3] == 1) ? 1 : 0;
    const float* H      = (const float*)d_in[0];
    const float* V      = (const float*)d_in[1];
    const float* Z      = (const float*)d_in[2];
    const float* H2d    = (const float*)d_in[3+o];
    const unsigned char* m2d = (const unsigned char*)d_in[4+o];
    const int*   E2didx = (const int*)d_in[5+o];
    const float* E2dfeat= (const float*)d_in[6+o];
    const float* Z3d    = (const float*)d_in[7+o];
    const unsigned char* m3d = (const unsigned char*)d_in[8+o];
    const int*   Edidx  = (const int*)d_in[9+o];
    const float* Edval  = (const float*)d_in[10+o];
    const float* virt   = (const float*)d_in[11+o];
    const float* ETe    = (const float*)d_in[12+o];
    const float* Wrbf   = (const float*)d_in[13+o];
    const float* We2d   = (const float*)d_in[14+o];
    const float* Wi     = (const float*)d_in[15+o];
    const float* Wphi1  = (const float*)d_in[16+o];
    const float* bphi1  = (const float*)d_in[17+o];
    const float* Wphi2  = (const float*)d_in[18+o];
    const float* bphi2  = (const float*)d_in[19+o];
    const float* Wmsg   = (const float*)d_in[20+o];
    const float* bmsg   = (const float*)d_in[21+o];
    float* out = (float*)d_out;

    cudaMemsetAsync(d_out, 0, (size_t)out_size * sizeof(float));
    k_pre<<<339, 256>>>(Wi, Wphi1, bphi1, We2d, Wrbf, ETe, virt, Wphi2, Wmsg);
    k_maskset<<<782, 256>>>(Edidx);
    k_nproj<<<1250, 128>>>(H, H2d);
    cudaFuncSetAttribute(k_edge, cudaFuncAttributeMaxDynamicSharedMemorySize,
                         (int)SMEM_EDGE);
    k_edge<<<NBT, 128, SMEM_EDGE>>>(E2didx, E2dfeat, Edidx, Edval, Z, Z3d, V,
                                    bphi2, bmsg, out);
    k_fin<<<(HN + 3*HN + 255)/256, 256>>>(out, m2d, m3d, HN + 3*HN);
}

// round 14
// speedup vs baseline: 1.8317x; 1.0809x over previous
#include <cuda_runtime.h>
#include <math.h>

#define NN   20000
#define E1C  100000
#define E2C  100000
#define HN   (NN*128)
#define CUTV 6.0f
#define PI_F 3.14159265358979f
#define XSL  196   /* 32x196 fp32 xs rows */
#define VGL  132   /* vg/rg buffer stride; 132%32=4 -> conflict-light */

#define NB0  3125
#define NB1  625
#define NB2  3125
#define NBT  (NB0+NB1+NB2)

typedef unsigned long long u64t;

/* ---------------- persistent device scratch ---------------- */
__device__ __align__(16) float g_WcT[256*128];
__device__ __align__(16) float g_Wc2dT[64*128];
__device__ __align__(16) float g_WcrbfT[64*128];
__device__ __align__(16) float g_etb[3*128];
__device__ __align__(16) float g_cvec[128];
__device__ __align__(16) float g_nproj[(size_t)2*NN*128];
/* pre-swizzled bf16 B fragments: [qc(3)][kt(12)][ntile(16)][lane(32)] x uint4
   .x/.y = hi pair, .z/.w = lo pair */
__device__ __align__(16) uint4 g_WfHL[576*32];
__device__ unsigned char g_mask[NN];

/* -------- packed f32x2 helpers -------- */
__device__ __forceinline__ u64t fma2d(u64t a, u64t b, u64t c) {
    u64t d; asm("fma.rn.f32x2 %0, %1, %2, %3;" : "=l"(d) : "l"(a), "l"(b), "l"(c));
    return d;
}
__device__ __forceinline__ u64t splat2(float x) {
    u64t d; asm("mov.b64 %0, {%1, %1};" : "=l"(d) : "r"(__float_as_uint(x)));
    return d;
}
__device__ __forceinline__ u64t fadd2(u64t a, u64t b) { return fma2d(a, splat2(1.0f), b); }
__device__ __forceinline__ float lo2(u64t d) { return __uint_as_float((unsigned)(d & 0xffffffffull)); }
__device__ __forceinline__ float hi2(u64t d) { return __uint_as_float((unsigned)(d >> 32)); }
__device__ __forceinline__ void red2(float* p, float a, float b) {
    asm volatile("red.global.add.v2.f32 [%0], {%1, %2};" :: "l"(p), "f"(a), "f"(b) : "memory");
}
__device__ __forceinline__ void red4(float* p, float a, float b, float c, float d) {
    asm volatile("red.global.add.v4.f32 [%0], {%1, %2, %3, %4};"
                 :: "l"(p), "f"(a), "f"(b), "f"(c), "f"(d) : "memory");
}
/* bf16x2 pack: low half = x, high half = y; plus hi/lo split */
__device__ __forceinline__ void bfsplit2(float x, float y, unsigned& hi, unsigned& lo) {
    unsigned h; asm("cvt.rn.bf16x2.f32 %0, %1, %2;" : "=r"(h) : "f"(y), "f"(x));
    float xh = __uint_as_float(h << 16);
    float yh = __uint_as_float(h & 0xffff0000u);
    asm("cvt.rn.bf16x2.f32 %0, %1, %2;" : "=r"(lo) : "f"(y - yh), "f"(x - xh));
    hi = h;
}
__device__ __forceinline__ void ldmA(unsigned a[4], unsigned saddr) {
    asm volatile("ldmatrix.sync.aligned.m8n8.x4.shared.b16 {%0,%1,%2,%3}, [%4];"
                 : "=r"(a[0]), "=r"(a[1]), "=r"(a[2]), "=r"(a[3]) : "r"(saddr));
}
__device__ __forceinline__ void mmabf(float* d, const unsigned a[4], unsigned bx, unsigned by) {
    asm volatile("mma.sync.aligned.m16n8k16.row.col.f32.bf16.bf16.f32 "
                 "{%0,%1,%2,%3}, {%4,%5,%6,%7}, {%8,%9}, {%0,%1,%2,%3};"
                 : "+f"(d[0]), "+f"(d[1]), "+f"(d[2]), "+f"(d[3])
                 : "r"(a[0]), "r"(a[1]), "r"(a[2]), "r"(a[3]), "r"(bx), "r"(by));
}

/* ---------------- fused precompute ---------------- */
__global__ void k_pre(const float* __restrict__ W_i, const float* __restrict__ W_phi1,
                      const float* __restrict__ b_phi1, const float* __restrict__ W_e2d,
                      const float* __restrict__ W_rbf, const float* __restrict__ ET,
                      const float* __restrict__ virt,
                      const float* __restrict__ W_phi2, const float* __restrict__ W_msg)
{
    int b = blockIdx.x;
    int t = threadIdx.x;
    if (b < 194) {
        int idx = b*256 + t;
        if (idx < NN) g_mask[idx] = 0;
        if (idx < 32768) {
            int k = idx >> 7, p = idx & 127;
            float s = 0.f;
            #pragma unroll 4
            for (int j = 0; j < 128; j++) s += W_phi1[p*288 + j] * W_i[j*256 + k];
            g_WcT[idx] = s;
        } else if (idx < 40960) {
            int i = idx - 32768; int k = i >> 7, p = i & 127;
            float s = 0.f;
            #pragma unroll 4
            for (int j = 0; j < 128; j++) s += W_phi1[p*288 + 128 + j] * W_e2d[j*64 + k];
            g_Wc2dT[i] = s;
        } else if (idx < 49152) {
            int i = idx - 40960; int k = i >> 7, p = i & 127;
            float s = 0.f;
            #pragma unroll 4
            for (int j = 0; j < 128; j++) s += W_phi1[p*288 + 128 + j] * W_rbf[j*64 + k];
            g_WcrbfT[i] = s;
        } else if (idx < 49536) {
            int i = idx - 49152; int tt = i >> 7, p = i & 127;
            float s = b_phi1[p];
            #pragma unroll
            for (int l = 0; l < 32; l++) s += W_phi1[p*288 + 256 + l] * ET[tt*32 + l];
            g_etb[i] = s;
        }
    } else if (b == 194) {
        __shared__ float u[128];
        if (t < 128) {
            float s = 0.f;
            #pragma unroll 4
            for (int j = 0; j < 128; j++) s += W_i[t*256 + 128 + j] * virt[j];
            u[t] = s;
        }
        __syncthreads();
        if (t < 128) {
            float c = 0.f;
            #pragma unroll 4
            for (int q = 0; q < 128; q++) c += W_phi1[t*288 + q] * u[q];
            g_cvec[t] = c;
        }
    } else {
        /* B fragment build: idx over 576 records x 32 lanes x 2 halves */
        int idx = (b - 195)*256 + t;
        if (idx < 36864) {
            int rec  = idx >> 6;
            int wi   = idx & 63;
            int lane = wi >> 1;
            int half = wi & 1;
            int nt = rec & 15;
            int kt = (rec >> 4) % 12;
            int qc = rec / 192;
            int ch = qc*128 + nt*8 + (lane >> 2);
            int k0 = kt*16 + (lane & 3)*2 + half*8;
            float w0, w1;
            if (k0 < 128) {
                w0 = W_phi2[(size_t)ch*128 + k0];
                w1 = W_phi2[(size_t)ch*128 + k0 + 1];
            } else {
                w0 = W_msg[(size_t)ch*64 + k0 - 128];
                w1 = W_msg[(size_t)ch*64 + k0 - 127];
            }
            unsigned hi, lo;
            bfsplit2(w0, w1, hi, lo);
            ((unsigned*)g_WfHL)[rec*128 + lane*4 + half]     = hi;
            ((unsigned*)g_WfHL)[rec*128 + lane*4 + 2 + half] = lo;
        }
    }
}

__global__ void k_maskset(const int* __restrict__ Edist_idx)
{
    int idx = blockIdx.x*256 + threadIdx.x;
    if (idx < 2*E2C) g_mask[Edist_idx[idx]] = 1;
}

/* ---------------- node projection (packed f32x2) ---------------- */
__global__ void __launch_bounds__(128) k_nproj(const float* __restrict__ H,
                                               const float* __restrict__ H2d)
{
    __shared__ float hx[16*128];
    __shared__ float h2[16*128];
    int t = threadIdx.x;
    int i0 = blockIdx.x * 16;
    #pragma unroll
    for (int it = 0; it < 16; it++) {
        int idx = t + it*128;
        int nd = idx >> 7, p = idx & 127;
        hx[idx] = H  [(size_t)(i0+nd)*128 + p];
        h2[idx] = H2d[(size_t)(i0+nd)*128 + p];
    }
    __syncthreads();
    int tn = t >> 6;            /* node half: 0/1 -> nodes tn*8.. */
    int tp = t & 63;            /* channel pair index */
    int p0 = tp * 2;
    const float* hxp = hx + tn*8*128;
    const float* h2p = h2 + tn*8*128;
    u64t a1[8], a2[8];
    #pragma unroll
    for (int nd = 0; nd < 8; nd++) { a1[nd] = 0; a2[nd] = 0; }
    #pragma unroll 2
    for (int k4 = 0; k4 < 128; k4 += 4) {
        float4 xv[8], yv[8];
        #pragma unroll
        for (int nd = 0; nd < 8; nd++) {
            xv[nd] = *(const float4*)(hxp + nd*128 + k4);
            yv[nd] = *(const float4*)(h2p + nd*128 + k4);
        }
        #pragma unroll
        for (int kk = 0; kk < 4; kk++) {
            u64t w1 = *(const u64t*)&g_WcT[(size_t)(k4+kk)*128 + p0];
            u64t w2 = *(const u64t*)&g_WcT[(size_t)(128+k4+kk)*128 + p0];
            #pragma unroll
            for (int nd = 0; nd < 8; nd++) {
                a1[nd] = fma2d(splat2(((const float*)&xv[nd])[kk]), w1, a1[nd]);
                a2[nd] = fma2d(splat2(((const float*)&yv[nd])[kk]), w2, a2[nd]);
            }
        }
    }
    u64t cv2 = *(const u64t*)&g_cvec[p0];
    #pragma unroll
    for (int nd = 0; nd < 8; nd++) {
        int node = i0 + tn*8 + nd;
        *(u64t*)&g_nproj[(size_t)node*128 + p0]      = fadd2(a1[nd], a2[nd]);
        *(u64t*)&g_nproj[(size_t)(NN+node)*128 + p0] = fadd2(a1[nd], cv2);
    }
}

/* ------- fp32 GEMM micro-kernel (phase A only) ------- */
__device__ __forceinline__ void gemm64g(const float* __restrict__ W, int ldw,
                                        const float* __restrict__ xsp,
                                        int c0, int c1, u64t (&acc)[4][4])
{
    #pragma unroll 2
    for (int k4 = 0; k4 < 64; k4 += 4) {
        float4 xv[4];
        #pragma unroll
        for (int j = 0; j < 4; j++)
            xv[j] = *(const float4*)(xsp + j*(4*XSL) + k4);
        #pragma unroll
        for (int kk = 0; kk < 4; kk++) {
            ulonglong2 wA = *(const ulonglong2*)(W + (size_t)(k4+kk)*ldw + c0);
            ulonglong2 wB = *(const ulonglong2*)(W + (size_t)(k4+kk)*ldw + c1);
            #pragma unroll
            for (int j = 0; j < 4; j++) {
                u64t a = splat2(((const float*)&xv[j])[kk]);
                acc[0][j] = fma2d(a, wA.x, acc[0][j]);
                acc[1][j] = fma2d(a, wA.y, acc[1][j]);
                acc[2][j] = fma2d(a, wB.x, acc[2][j]);
                acc[3][j] = fma2d(a, wB.y, acc[3][j]);
            }
        }
    }
}

/* ---------------- fused per-edge kernel: 32 edges / 128 threads ---------------- */
__global__ void __launch_bounds__(128, 3) k_edge(
    const int* __restrict__ E2d_idx, const float* __restrict__ E2d_feat,
    const int* __restrict__ Edist_idx, const float* __restrict__ Edist_val,
    const float* __restrict__ Z, const float* __restrict__ Z3d,
    const float* __restrict__ V,
    const float* __restrict__ b_phi2, const float* __restrict__ b_msg,
    float* __restrict__ out)
{
    extern __shared__ float sm[];
    float*    smxs  = sm;                             /* 32 x 196 fp32 (dead after cvt) */
    float*    rgbuf = sm;                             /* alias */
    unsigned* xshiw = (unsigned*)(sm + 32*XSL);       /* 32 x 100 u32 (bf16x2) */
    unsigned* xslow = xshiw + 3200;                   /* 32 x 100 u32 */
    float*    vgbuf = (float*)(xslow + 3200);         /* 32 x 132 */
    int*   srow  = (int*)(vgbuf + 32*VGL);
    int*   scol  = srow + 32;
    float* sdist = (float*)(scol + 32);
    float* senvd = sdist + 32;
    float* sdval = senvd + 32;
    float* senv2 = sdval + 32;
    float* sunit = senv2 + 32;                        /* 32 x 3 */

    int t  = threadIdx.x;
    int w  = t >> 5;
    int l  = t & 31;
    int tp = l & 7;
    int te = l >> 3;
    int cb = (w & 1) * 64;
    int eb = (w >> 1) * 16;
    int c0 = cb + tp*4;
    int c1 = cb + 32 + tp*4;
    int ebte = eb + te;

    int bid = blockIdx.x;
    int base = bid * 32;
    int type = (bid < NB0) ? 0 : (bid < NB0+NB1 ? 1 : 2);

    /* --- metadata + geometry (warp 0) --- */
    if (t < 32) {
        int eg = base + t;
        int row, col; float dval = 0.f;
        if (type == 0)      { row = E2d_idx[eg]; col = E2d_idx[E1C + eg]; }
        else if (type == 1) { int i = eg - E1C; row = i; col = NN + i; }
        else                { int j = eg - E1C - NN; row = Edist_idx[j];
                              col = Edist_idx[E2C + j]; dval = Edist_val[j]; }
        srow[t] = row; scol[t] = col; sdval[t] = dval;
        float zr0 = Z[row*3+0], zr1 = Z[row*3+1], zr2 = Z[row*3+2];
        float zc0, zc1, zc2;
        if (col < NN) { zc0 = Z[col*3+0]; zc1 = Z[col*3+1]; zc2 = Z[col*3+2]; }
        else { int c2 = col - NN; zc0 = Z3d[c2*3+0]; zc1 = Z3d[c2*3+1]; zc2 = Z3d[c2*3+2]; }
        float r0 = zr0-zc0, r1 = zr1-zc1, r2 = zr2-zc2;
        float d = sqrtf(r0*r0 + r1*r1 + r2*r2 + 1e-8f);
        sdist[t] = d;
        float inv = 1.0f / d;
        sunit[t*3+0] = r0*inv; sunit[t*3+1] = r1*inv; sunit[t*3+2] = r2*inv;
        float cl = fminf(d * (1.0f/CUTV), 1.0f);
        senvd[t] = 0.5f * (cosf(PI_F*cl) + 1.0f);
        float cl2 = fminf(fmaxf(dval * (1.0f/CUTV), 0.f), 1.0f);
        senv2[t] = 0.5f * (cosf(PI_F*cl2) + 1.0f);
    }
    __syncthreads();

    /* --- per-edge 64-dim features into xs[e][128..191] --- */
    const float cstep = CUTV / 63.0f;
    const float i2w2  = 1.0f / (2.0f * (CUTV/64.0f) * (CUTV/64.0f));
    if (type == 0) {
        #pragma unroll
        for (int it = 0; it < 16; it++) {
            int idx = t + it*128; int e = idx & 31, k = idx >> 5;
            smxs[e*XSL + 128 + k] = E2d_feat[(size_t)k*E1C + base + e];
        }
    } else if (type == 2) {
        #pragma unroll
        for (int it = 0; it < 16; it++) {
            int idx = t + it*128; int e = idx & 31, k = idx >> 5;
            float diff = sdval[e] - k*cstep;
            smxs[e*XSL + 128 + k] = expf(-diff*diff*i2w2) * senv2[e];
        }
    }
    /* --- gather node projection + edge-type bias --- */
    u64t gn[4][4];
    #pragma unroll
    for (int j = 0; j < 4; j++) {
        const float* np = g_nproj + (size_t)scol[ebte + 4*j]*128;
        ulonglong2 ga = *(const ulonglong2*)(np + c0);
        ulonglong2 gb = *(const ulonglong2*)(np + c1);
        gn[0][j] = ga.x; gn[1][j] = ga.y; gn[2][j] = gb.x; gn[3][j] = gb.y;
    }
    u64t et2[4];
    {
        ulonglong2 ea = *(const ulonglong2*)(g_etb + type*128 + c0);
        ulonglong2 eb2 = *(const ulonglong2*)(g_etb + type*128 + c1);
        et2[0] = ea.x; et2[1] = ea.y; et2[2] = eb2.x; et2[3] = eb2.y;
    }
    __syncthreads();

    /* --- phase A (fp32): act = nproj[col] + etb (+ feats @ Wtype^T); silu --- */
    {
        u64t acc[4][4] = {};
        if (type == 0)
            gemm64g(g_Wc2dT, 128, smxs + ebte*XSL + 128, c0, c1, acc);
        else if (type == 2)
            gemm64g(g_WcrbfT, 128, smxs + ebte*XSL + 128, c0, c1, acc);
        #pragma unroll
        for (int j = 0; j < 4; j++) {
            int e = ebte + 4*j;
            float v[8];
            #pragma unroll
            for (int q = 0; q < 4; q++) {
                u64t s = fadd2(acc[q][j], fadd2(gn[q][j], et2[q]));
                float a = lo2(s), b = hi2(s);
                v[2*q]   = a / (1.0f + expf(-a));
                v[2*q+1] = b / (1.0f + expf(-b));
            }
            *(float4*)&smxs[e*XSL + c0] = make_float4(v[0], v[1], v[2], v[3]);
            *(float4*)&smxs[e*XSL + c1] = make_float4(v[4], v[5], v[6], v[7]);
        }
    }
    __syncthreads();

    /* --- geometric RBF overwrites feats --- */
    #pragma unroll
    for (int it = 0; it < 16; it++) {
        int idx = t + it*128; int e = idx & 31, k = idx >> 5;
        float diff = sdist[e] - k*cstep;
        smxs[e*XSL + 128 + k] = expf(-diff*diff*i2w2) * senvd[e];
    }
    __syncthreads();

    /* --- convert xs fp32 -> bf16 hi/lo (rows padded to 200 bf16 = 400B) --- */
    #pragma unroll
    for (int it = 0; it < 24; it++) {
        int lin = t + it*128;
        int e  = lin / 96;
        int kp = lin % 96;
        float2 v = *(const float2*)&smxs[e*XSL + kp*2];
        unsigned hi, lo;
        bfsplit2(v.x, v.y, hi, lo);
        xshiw[e*100 + kp] = hi;
        xslow[e*100 + kp] = lo;
    }
    __syncthreads();   /* smxs now dead -> rgbuf alias is safe */

    /* --- phase C: kt-major bf16x3 tensor GEMM; qc order {1,2,0} --- */
    unsigned xshi_s = (unsigned)__cvta_generic_to_shared(xshiw);
    unsigned xslo_s = (unsigned)__cvta_generic_to_shared(xslow);
    unsigned a_off  = (unsigned)((l & 15)*400 + (l >> 4)*16);

    #pragma unroll 1
    for (int qi = 0; qi < 3; qi++) {
        int qc = (qi == 0) ? 1 : (qi == 1 ? 2 : 0);
        float accP[2][4][4], accW[2][4][4];
        #pragma unroll
        for (int mt = 0; mt < 2; mt++)
            #pragma unroll
            for (int nt = 0; nt < 4; nt++)
                #pragma unroll
                for (int r = 0; r < 4; r++) { accP[mt][nt][r] = 0.f; accW[mt][nt][r] = 0.f; }

        const uint4* WB = g_WfHL + l;
        int recb = (qc*12)*16 + (w << 2);

        #pragma unroll 4
        for (int kt = 0; kt < 8; kt++) {          /* accP: k 0..127 */
            uint4 bv[4];
            #pragma unroll
            for (int nt = 0; nt < 4; nt++)
                bv[nt] = WB[(size_t)(recb + kt*16 + nt)*32];
            unsigned ah0[4], ah1[4], al0[4], al1[4];
            ldmA(ah0, xshi_s + a_off + kt*32);
            ldmA(ah1, xshi_s + a_off + kt*32 + 6400);
            ldmA(al0, xslo_s + a_off + kt*32);
            ldmA(al1, xslo_s + a_off + kt*32 + 6400);
            #pragma unroll
            for (int nt = 0; nt < 4; nt++) {
                mmabf(accP[0][nt], ah0, bv[nt].x, bv[nt].y);
                mmabf(accP[1][nt], ah1, bv[nt].x, bv[nt].y);
                mmabf(accP[0][nt], ah0, bv[nt].z, bv[nt].w);
                mmabf(accP[1][nt], ah1, bv[nt].z, bv[nt].w);
                mmabf(accP[0][nt], al0, bv[nt].x, bv[nt].y);
                mmabf(accP[1][nt], al1, bv[nt].x, bv[nt].y);
            }
        }
        #pragma unroll 4
        for (int kt = 8; kt < 12; kt++) {         /* accW: k 128..191 */
            uint4 bv[4];
            #pragma unroll
            for (int nt = 0; nt < 4; nt++)
                bv[nt] = WB[(size_t)(recb + kt*16 + nt)*32];
            unsigned ah0[4], ah1[4], al0[4], al1[4];
            ldmA(ah0, xshi_s + a_off + kt*32);
            ldmA(ah1, xshi_s + a_off + kt*32 + 6400);
            ldmA(al0, xslo_s + a_off + kt*32);
            ldmA(al1, xslo_s + a_off + kt*32 + 6400);
            #pragma unroll
            for (int nt = 0; nt < 4; nt++) {
                mmabf(accW[0][nt], ah0, bv[nt].x, bv[nt].y);
                mmabf(accW[1][nt], ah1, bv[nt].x, bv[nt].y);
                mmabf(accW[0][nt], ah0, bv[nt].z, bv[nt].w);
                mmabf(accW[1][nt], ah1, bv[nt].z, bv[nt].w);
                mmabf(accW[0][nt], al0, bv[nt].x, bv[nt].y);
                mmabf(accW[1][nt], al1, bv[nt].x, bv[nt].y);
            }
        }

        /* epilogue */
        #pragma unroll
        for (int nt = 0; nt < 4; nt++) {
            int ch0 = (w << 5) + (nt << 3) + ((l & 3) << 1);
            float2 bp = *(const float2*)&b_phi2[qc*128 + ch0];
            float2 bm = *(const float2*)&b_msg [qc*128 + ch0];
            #pragma unroll
            for (int mt = 0; mt < 2; mt++) {
                float m0 = (accP[mt][nt][0] + bp.x) * (accW[mt][nt][0] + bm.x);
                float m1 = (accP[mt][nt][1] + bp.y) * (accW[mt][nt][1] + bm.y);
                float m2 = (accP[mt][nt][2] + bp.x) * (accW[mt][nt][2] + bm.x);
                float m3 = (accP[mt][nt][3] + bp.y) * (accW[mt][nt][3] + bm.y);
                int e1 = (mt << 4) + (l >> 2);
                int e2 = e1 + 8;
                if (qc == 1) {
                    *(float2*)&vgbuf[e1*VGL + ch0] = make_float2(m0, m1);
                    *(float2*)&vgbuf[e2*VGL + ch0] = make_float2(m2, m3);
                } else if (qc == 2) {
                    *(float2*)&rgbuf[e1*VGL + ch0] = make_float2(m0, m1);
                    *(float2*)&rgbuf[e2*VGL + ch0] = make_float2(m2, m3);
                } else { /* qc == 0 : H scatter (sector-optimal) */
                    red2(out + (size_t)srow[e1]*128 + ch0, m0, m1);
                    red2(out + (size_t)srow[e2]*128 + ch0, m2, m3);
                }
            }
        }
    }

    /* --- cooperative V pass: coalesced gather + red4 scatter --- */
    __syncthreads();
    {
        int e   = t >> 2;
        int seg = t & 3;
        int row = srow[e], col = scol[e];
        float u0 = sunit[e*3+0], u1 = sunit[e*3+1], u2 = sunit[e*3+2];
        int r0 = seg % 3;
        float ua = (r0==0) ? u0 : ((r0==1) ? u1 : u2);
        float ub = (r0==0) ? u1 : ((r0==1) ? u2 : u0);
        float uc = (r0==0) ? u2 : ((r0==1) ? u0 : u1);
        const float* vrow = V + (size_t)col*384;
        float* op = out + HN + (size_t)row*384;
        const float* vgr = vgbuf + e*VGL;
        const float* rgr = rgbuf + e*VGL;
        int ch = (seg == 3) ? 4 : seg;
        int r  = r0;
        #pragma unroll
        for (int i = 0; i < 24; i++) {
            int fo = 4*seg + 16*i;
            float4 vb;
            if (type != 1) vb = *(const float4*)(vrow + fo);
            else           vb = make_float4(0.f, 0.f, 0.f, 0.f);
            float vga = vgr[ch], vgb2 = vgr[ch+1];
            float rga = rgr[ch], rgb2 = rgr[ch+1];
            float uA, uB, uC;
            if (i % 3 == 0)      { uA = ua; uB = ub; uC = uc; }
            else if (i % 3 == 1) { uA = ub; uB = uc; uC = ua; }
            else                 { uA = uc; uB = ua; uC = ub; }
            bool cB = (r == 2);
            bool cC = (r >= 1);
            float vg1 = cB ? vgb2 : vga, rg1 = cB ? rgb2 : rga;
            float vg2 = cC ? vgb2 : vga, rg2 = cC ? rgb2 : rga;
            float dx = vb.x*vga + uA*rga;
            float dy = vb.y*vg1 + uB*rg1;
            float dz = vb.z*vg2 + uC*rg2;
            float dw = vb.w*vgb2 + uA*rgb2;
            red4(op + fo, dx, dy, dz, dw);
            ch += (r == 2) ? 6 : 5;
            r   = (r == 2) ? 0 : r + 1;
        }
    }
}

/* ---------------- finalize ---------------- */
__global__ void k_fin(float* __restrict__ out,
                      const unsigned char* __restrict__ m2d,
                      const unsigned char* __restrict__ m3d, int total)
{
    int idx = blockIdx.x*256 + threadIdx.x;
    if (idx >= total) return;
    int i = (idx < HN) ? (idx >> 7) : ((idx - HN) / 384);
    float v = out[idx];
    v = fminf(fmaxf(v, -100.f), 100.f);
    bool keep = ((m2d[i] | m3d[i] | g_mask[i]) != 0);
    out[idx] = keep ? v : 0.f;
}

#define SMEM_EDGE ((32*XSL + 3200 + 3200 + 32*VGL + 2*32 + 4*32 + 96 + 32) * sizeof(float))

extern "C" void kernel_launch(void* const* d_in, const int* in_sizes, int n_in,
                              void* d_out, int out_size)
{
    int o = (in_sizes[3] == 1) ? 1 : 0;
    const float* H      = (const float*)d_in[0];
    const float* V      = (const float*)d_in[1];
    const float* Z      = (const float*)d_in[2];
    const float* H2d    = (const float*)d_in[3+o];
    const unsigned char* m2d = (const unsigned char*)d_in[4+o];
    const int*   E2didx = (const int*)d_in[5+o];
    const float* E2dfeat= (const float*)d_in[6+o];
    const float* Z3d    = (const float*)d_in[7+o];
    const unsigned char* m3d = (const unsigned char*)d_in[8+o];
    const int*   Edidx  = (const int*)d_in[9+o];
    const float* Edval  = (const float*)d_in[10+o];
    const float* virt   = (const float*)d_in[11+o];
    const float* ETe    = (const float*)d_in[12+o];
    const float* Wrbf   = (const float*)d_in[13+o];
    const float* We2d   = (const float*)d_in[14+o];
    const float* Wi     = (const float*)d_in[15+o];
    const float* Wphi1  = (const float*)d_in[16+o];
    const float* bphi1  = (const float*)d_in[17+o];
    const float* Wphi2  = (const float*)d_in[18+o];
    const float* bphi2  = (const float*)d_in[19+o];
    const float* Wmsg   = (const float*)d_in[20+o];
    const float* bmsg   = (const float*)d_in[21+o];
    float* out = (float*)d_out;

    cudaMemsetAsync(d_out, 0, (size_t)out_size * sizeof(float));
    k_pre<<<339, 256>>>(Wi, Wphi1, bphi1, We2d, Wrbf, ETe, virt, Wphi2, Wmsg);
    k_maskset<<<782, 256>>>(Edidx);
    k_nproj<<<1250, 128>>>(H, H2d);
    cudaFuncSetAttribute(k_edge, cudaFuncAttributeMaxDynamicSharedMemorySize,
                         (int)SMEM_EDGE);
    k_edge<<<NBT, 128, SMEM_EDGE>>>(E2didx, E2dfeat, Edidx, Edval, Z, Z3d, V,
                                    bphi2, bmsg, out);
    k_fin<<<(HN + 3*HN + 255)/256, 256>>>(out, m2d, m3d, HN + 3*HN);
}

// round 16
// speedup vs baseline: 1.8577x; 1.0142x over previous
#include <cuda_runtime.h>
#include <math.h>

#define NN   20000
#define E1C  100000
#define E2C  100000
#define HN   (NN*128)
#define CUTV 6.0f
#define PI_F 3.14159265358979f
#define XSL  196   /* 32x196 fp32 xs rows */
#define VGL  132   /* vg/rg buffer stride; 132%32=4 -> conflict-light */

#define NB0  3125
#define NB1  625
#define NB2  3125
#define NBT  (NB0+NB1+NB2)

typedef unsigned long long u64t;

/* ---------------- persistent device scratch ---------------- */
__device__ __align__(16) float g_WcT[256*128];
__device__ __align__(16) float g_Wc2dT[64*128];
__device__ __align__(16) float g_WcrbfT[64*128];
__device__ __align__(16) float g_etb[3*128];
__device__ __align__(16) float g_cvec[128];
__device__ __align__(16) float g_nproj[(size_t)2*NN*128];
/* pre-swizzled bf16 B fragments: [qc(3)][kt(12)][ntile(16)][lane(32)] x uint4
   .x/.y = hi pair, .z/.w = lo pair */
__device__ __align__(16) uint4 g_WfHL[576*32];
__device__ unsigned char g_mask[NN];

/* -------- packed f32x2 helpers -------- */
__device__ __forceinline__ u64t fma2d(u64t a, u64t b, u64t c) {
    u64t d; asm("fma.rn.f32x2 %0, %1, %2, %3;" : "=l"(d) : "l"(a), "l"(b), "l"(c));
    return d;
}
__device__ __forceinline__ u64t splat2(float x) {
    u64t d; asm("mov.b64 %0, {%1, %1};" : "=l"(d) : "r"(__float_as_uint(x)));
    return d;
}
__device__ __forceinline__ u64t fadd2(u64t a, u64t b) { return fma2d(a, splat2(1.0f), b); }
__device__ __forceinline__ float lo2(u64t d) { return __uint_as_float((unsigned)(d & 0xffffffffull)); }
__device__ __forceinline__ float hi2(u64t d) { return __uint_as_float((unsigned)(d >> 32)); }
__device__ __forceinline__ void red2(float* p, float a, float b) {
    asm volatile("red.global.add.v2.f32 [%0], {%1, %2};" :: "l"(p), "f"(a), "f"(b) : "memory");
}
__device__ __forceinline__ void red4(float* p, float a, float b, float c, float d) {
    asm volatile("red.global.add.v4.f32 [%0], {%1, %2, %3, %4};"
                 :: "l"(p), "f"(a), "f"(b), "f"(c), "f"(d) : "memory");
}
/* bf16x2 pack: low half = x, high half = y; plus hi/lo split */
__device__ __forceinline__ void bfsplit2(float x, float y, unsigned& hi, unsigned& lo) {
    unsigned h; asm("cvt.rn.bf16x2.f32 %0, %1, %2;" : "=r"(h) : "f"(y), "f"(x));
    float xh = __uint_as_float(h << 16);
    float yh = __uint_as_float(h & 0xffff0000u);
    asm("cvt.rn.bf16x2.f32 %0, %1, %2;" : "=r"(lo) : "f"(y - yh), "f"(x - xh));
    hi = h;
}
__device__ __forceinline__ void ldmA(unsigned a[4], unsigned saddr) {
    asm volatile("ldmatrix.sync.aligned.m8n8.x4.shared.b16 {%0,%1,%2,%3}, [%4];"
                 : "=r"(a[0]), "=r"(a[1]), "=r"(a[2]), "=r"(a[3]) : "r"(saddr));
}
__device__ __forceinline__ void mmabf(float* d, const unsigned a[4], unsigned bx, unsigned by) {
    asm volatile("mma.sync.aligned.m16n8k16.row.col.f32.bf16.bf16.f32 "
                 "{%0,%1,%2,%3}, {%4,%5,%6,%7}, {%8,%9}, {%0,%1,%2,%3};"
                 : "+f"(d[0]), "+f"(d[1]), "+f"(d[2]), "+f"(d[3])
                 : "r"(a[0]), "r"(a[1]), "r"(a[2]), "r"(a[3]), "r"(bx), "r"(by));
}

/* ---------------- fused precompute ---------------- */
__global__ void k_pre(const float* __restrict__ W_i, const float* __restrict__ W_phi1,
                      const float* __restrict__ b_phi1, const float* __restrict__ W_e2d,
                      const float* __restrict__ W_rbf, const float* __restrict__ ET,
                      const float* __restrict__ virt,
                      const float* __restrict__ W_phi2, const float* __restrict__ W_msg)
{
    int b = blockIdx.x;
    int t = threadIdx.x;
    if (b < 194) {
        int idx = b*256 + t;
        if (idx < NN) g_mask[idx] = 0;
        if (idx < 32768) {
            int k = idx >> 7, p = idx & 127;
            float s = 0.f;
            #pragma unroll 4
            for (int j = 0; j < 128; j++) s += W_phi1[p*288 + j] * W_i[j*256 + k];
            g_WcT[idx] = s;
        } else if (idx < 40960) {
            int i = idx - 32768; int k = i >> 7, p = i & 127;
            float s = 0.f;
            #pragma unroll 4
            for (int j = 0; j < 128; j++) s += W_phi1[p*288 + 128 + j] * W_e2d[j*64 + k];
            g_Wc2dT[i] = s;
        } else if (idx < 49152) {
            int i = idx - 40960; int k = i >> 7, p = i & 127;
            float s = 0.f;
            #pragma unroll 4
            for (int j = 0; j < 128; j++) s += W_phi1[p*288 + 128 + j] * W_rbf[j*64 + k];
            g_WcrbfT[i] = s;
        } else if (idx < 49536) {
            int i = idx - 49152; int tt = i >> 7, p = i & 127;
            float s = b_phi1[p];
            #pragma unroll
            for (int l = 0; l < 32; l++) s += W_phi1[p*288 + 256 + l] * ET[tt*32 + l];
            g_etb[i] = s;
        }
    } else if (b == 194) {
        __shared__ float u[128];
        if (t < 128) {
            float s = 0.f;
            #pragma unroll 4
            for (int j = 0; j < 128; j++) s += W_i[t*256 + 128 + j] * virt[j];
            u[t] = s;
        }
        __syncthreads();
        if (t < 128) {
            float c = 0.f;
            #pragma unroll 4
            for (int q = 0; q < 128; q++) c += W_phi1[t*288 + q] * u[q];
            g_cvec[t] = c;
        }
    } else {
        /* B fragment build: idx over 576 records x 32 lanes x 2 halves */
        int idx = (b - 195)*256 + t;
        if (idx < 36864) {
            int rec  = idx >> 6;
            int wi   = idx & 63;
            int lane = wi >> 1;
            int half = wi & 1;
            int nt = rec & 15;
            int kt = (rec >> 4) % 12;
            int qc = rec / 192;
            int ch = qc*128 + nt*8 + (lane >> 2);
            int k0 = kt*16 + (lane & 3)*2 + half*8;
            float w0, w1;
            if (k0 < 128) {
                w0 = W_phi2[(size_t)ch*128 + k0];
                w1 = W_phi2[(size_t)ch*128 + k0 + 1];
            } else {
                w0 = W_msg[(size_t)ch*64 + k0 - 128];
                w1 = W_msg[(size_t)ch*64 + k0 - 127];
            }
            unsigned hi, lo;
            bfsplit2(w0, w1, hi, lo);
            ((unsigned*)g_WfHL)[rec*128 + lane*4 + half]     = hi;
            ((unsigned*)g_WfHL)[rec*128 + lane*4 + 2 + half] = lo;
        }
    }
}

__global__ void k_maskset(const int* __restrict__ Edist_idx)
{
    int idx = blockIdx.x*256 + threadIdx.x;
    if (idx < 2*E2C) g_mask[Edist_idx[idx]] = 1;
}

/* ---------------- node projection (packed f32x2) ---------------- */
__global__ void __launch_bounds__(128) k_nproj(const float* __restrict__ H,
                                               const float* __restrict__ H2d)
{
    __shared__ float hx[16*128];
    __shared__ float h2[16*128];
    int t = threadIdx.x;
    int i0 = blockIdx.x * 16;
    #pragma unroll
    for (int it = 0; it < 16; it++) {
        int idx = t + it*128;
        int nd = idx >> 7, p = idx & 127;
        hx[idx] = H  [(size_t)(i0+nd)*128 + p];
        h2[idx] = H2d[(size_t)(i0+nd)*128 + p];
    }
    __syncthreads();
    int tn = t >> 6;
    int tp = t & 63;
    int p0 = tp * 2;
    const float* hxp = hx + tn*8*128;
    const float* h2p = h2 + tn*8*128;
    u64t a1[8], a2[8];
    #pragma unroll
    for (int nd = 0; nd < 8; nd++) { a1[nd] = 0; a2[nd] = 0; }
    #pragma unroll 2
    for (int k4 = 0; k4 < 128; k4 += 4) {
        float4 xv[8], yv[8];
        #pragma unroll
        for (int nd = 0; nd < 8; nd++) {
            xv[nd] = *(const float4*)(hxp + nd*128 + k4);
            yv[nd] = *(const float4*)(h2p + nd*128 + k4);
        }
        #pragma unroll
        for (int kk = 0; kk < 4; kk++) {
            u64t w1 = *(const u64t*)&g_WcT[(size_t)(k4+kk)*128 + p0];
            u64t w2 = *(const u64t*)&g_WcT[(size_t)(128+k4+kk)*128 + p0];
            #pragma unroll
            for (int nd = 0; nd < 8; nd++) {
                a1[nd] = fma2d(splat2(((const float*)&xv[nd])[kk]), w1, a1[nd]);
                a2[nd] = fma2d(splat2(((const float*)&yv[nd])[kk]), w2, a2[nd]);
            }
        }
    }
    u64t cv2 = *(const u64t*)&g_cvec[p0];
    #pragma unroll
    for (int nd = 0; nd < 8; nd++) {
        int node = i0 + tn*8 + nd;
        *(u64t*)&g_nproj[(size_t)node*128 + p0]      = fadd2(a1[nd], a2[nd]);
        *(u64t*)&g_nproj[(size_t)(NN+node)*128 + p0] = fadd2(a1[nd], cv2);
    }
}

/* ------- fp32 GEMM micro-kernel (phase A only) ------- */
__device__ __forceinline__ void gemm64g(const float* __restrict__ W, int ldw,
                                        const float* __restrict__ xsp,
                                        int c0, int c1, u64t (&acc)[4][4])
{
    #pragma unroll 2
    for (int k4 = 0; k4 < 64; k4 += 4) {
        float4 xv[4];
        #pragma unroll
        for (int j = 0; j < 4; j++)
            xv[j] = *(const float4*)(xsp + j*(4*XSL) + k4);
        #pragma unroll
        for (int kk = 0; kk < 4; kk++) {
            ulonglong2 wA = *(const ulonglong2*)(W + (size_t)(k4+kk)*ldw + c0);
            ulonglong2 wB = *(const ulonglong2*)(W + (size_t)(k4+kk)*ldw + c1);
            #pragma unroll
            for (int j = 0; j < 4; j++) {
                u64t a = splat2(((const float*)&xv[j])[kk]);
                acc[0][j] = fma2d(a, wA.x, acc[0][j]);
                acc[1][j] = fma2d(a, wA.y, acc[1][j]);
                acc[2][j] = fma2d(a, wB.x, acc[2][j]);
                acc[3][j] = fma2d(a, wB.y, acc[3][j]);
            }
        }
    }
}

/* ---------------- fused per-edge kernel: 32 edges / 128 threads ---------------- */
__global__ void __launch_bounds__(128, 4) k_edge(
    const int* __restrict__ E2d_idx, const float* __restrict__ E2d_feat,
    const int* __restrict__ Edist_idx, const float* __restrict__ Edist_val,
    const float* __restrict__ Z, const float* __restrict__ Z3d,
    const float* __restrict__ V,
    const float* __restrict__ b_phi2, const float* __restrict__ b_msg,
    float* __restrict__ out)
{
    extern __shared__ float sm[];
    float*    smxs  = sm;                             /* 32 x 196 fp32 (dead after cvt) */
    float*    vgbuf = sm;                             /* alias over smxs: 4224 <= 6272  */
    unsigned* xshiw = (unsigned*)(sm + 32*XSL);       /* 32 x 100 u32 (bf16x2 hi) */
    unsigned* xslow = xshiw + 3200;                   /* 32 x 100 u32 (bf16x2 lo) */
    float*    rgbuf = (float*)xshiw;                  /* alias over xshiw+xslow: 4224 <= 6400 */
    int*   srow  = (int*)(xslow + 3200);
    int*   scol  = srow + 32;
    float* sdist = (float*)(scol + 32);
    float* senvd = sdist + 32;
    float* sdval = senvd + 32;
    float* senv2 = sdval + 32;
    float* sunit = senv2 + 32;                        /* 32 x 3 */

    int t  = threadIdx.x;
    int w  = t >> 5;
    int l  = t & 31;
    int tp = l & 7;
    int te = l >> 3;
    int cb = (w & 1) * 64;
    int eb = (w >> 1) * 16;
    int c0 = cb + tp*4;
    int c1 = cb + 32 + tp*4;
    int ebte = eb + te;

    int bid = blockIdx.x;
    int base = bid * 32;
    int type = (bid < NB0) ? 0 : (bid < NB0+NB1 ? 1 : 2);

    /* --- metadata + geometry (warp 0) --- */
    if (t < 32) {
        int eg = base + t;
        int row, col; float dval = 0.f;
        if (type == 0)      { row = E2d_idx[eg]; col = E2d_idx[E1C + eg]; }
        else if (type == 1) { int i = eg - E1C; row = i; col = NN + i; }
        else                { int j = eg - E1C - NN; row = Edist_idx[j];
                              col = Edist_idx[E2C + j]; dval = Edist_val[j]; }
        srow[t] = row; scol[t] = col; sdval[t] = dval;
        float zr0 = Z[row*3+0], zr1 = Z[row*3+1], zr2 = Z[row*3+2];
        float zc0, zc1, zc2;
        if (col < NN) { zc0 = Z[col*3+0]; zc1 = Z[col*3+1]; zc2 = Z[col*3+2]; }
        else { int c2 = col - NN; zc0 = Z3d[c2*3+0]; zc1 = Z3d[c2*3+1]; zc2 = Z3d[c2*3+2]; }
        float r0 = zr0-zc0, r1 = zr1-zc1, r2 = zr2-zc2;
        float d = sqrtf(r0*r0 + r1*r1 + r2*r2 + 1e-8f);
        sdist[t] = d;
        float inv = 1.0f / d;
        sunit[t*3+0] = r0*inv; sunit[t*3+1] = r1*inv; sunit[t*3+2] = r2*inv;
        float cl = fminf(d * (1.0f/CUTV), 1.0f);
        senvd[t] = 0.5f * (cosf(PI_F*cl) + 1.0f);
        float cl2 = fminf(fmaxf(dval * (1.0f/CUTV), 0.f), 1.0f);
        senv2[t] = 0.5f * (cosf(PI_F*cl2) + 1.0f);
    }
    __syncthreads();

    /* --- per-edge 64-dim features into xs[e][128..191] --- */
    const float cstep = CUTV / 63.0f;
    const float i2w2  = 1.0f / (2.0f * (CUTV/64.0f) * (CUTV/64.0f));
    if (type == 0) {
        #pragma unroll
        for (int it = 0; it < 16; it++) {
            int idx = t + it*128; int e = idx & 31, k = idx >> 5;
            smxs[e*XSL + 128 + k] = E2d_feat[(size_t)k*E1C + base + e];
        }
    } else if (type == 2) {
        #pragma unroll
        for (int it = 0; it < 16; it++) {
            int idx = t + it*128; int e = idx & 31, k = idx >> 5;
            float diff = sdval[e] - k*cstep;
            smxs[e*XSL + 128 + k] = expf(-diff*diff*i2w2) * senv2[e];
        }
    }
    /* --- gather node projection + edge-type bias --- */
    u64t gn[4][4];
    #pragma unroll
    for (int j = 0; j < 4; j++) {
        const float* np = g_nproj + (size_t)scol[ebte + 4*j]*128;
        ulonglong2 ga = *(const ulonglong2*)(np + c0);
        ulonglong2 gb = *(const ulonglong2*)(np + c1);
        gn[0][j] = ga.x; gn[1][j] = ga.y; gn[2][j] = gb.x; gn[3][j] = gb.y;
    }
    u64t et2[4];
    {
        ulonglong2 ea = *(const ulonglong2*)(g_etb + type*128 + c0);
        ulonglong2 eb2 = *(const ulonglong2*)(g_etb + type*128 + c1);
        et2[0] = ea.x; et2[1] = ea.y; et2[2] = eb2.x; et2[3] = eb2.y;
    }
    __syncthreads();

    /* --- phase A (fp32): act = nproj[col] + etb (+ feats @ Wtype^T); silu --- */
    {
        u64t acc[4][4] = {};
        if (type == 0)
            gemm64g(g_Wc2dT, 128, smxs + ebte*XSL + 128, c0, c1, acc);
        else if (type == 2)
            gemm64g(g_WcrbfT, 128, smxs + ebte*XSL + 128, c0, c1, acc);
        #pragma unroll
        for (int j = 0; j < 4; j++) {
            int e = ebte + 4*j;
            float v[8];
            #pragma unroll
            for (int q = 0; q < 4; q++) {
                u64t s = fadd2(acc[q][j], fadd2(gn[q][j], et2[q]));
                float a = lo2(s), b = hi2(s);
                v[2*q]   = a / (1.0f + expf(-a));
                v[2*q+1] = b / (1.0f + expf(-b));
            }
            *(float4*)&smxs[e*XSL + c0] = make_float4(v[0], v[1], v[2], v[3]);
            *(float4*)&smxs[e*XSL + c1] = make_float4(v[4], v[5], v[6], v[7]);
        }
    }
    __syncthreads();

    /* --- geometric RBF overwrites feats --- */
    #pragma unroll
    for (int it = 0; it < 16; it++) {
        int idx = t + it*128; int e = idx & 31, k = idx >> 5;
        float diff = sdist[e] - k*cstep;
        smxs[e*XSL + 128 + k] = expf(-diff*diff*i2w2) * senvd[e];
    }
    __syncthreads();

    /* --- convert xs fp32 -> bf16 hi/lo (rows padded to 200 bf16 = 400B) --- */
    #pragma unroll
    for (int it = 0; it < 24; it++) {
        int lin = t + it*128;
        int e  = lin / 96;
        int kp = lin % 96;
        float2 v = *(const float2*)&smxs[e*XSL + kp*2];
        unsigned hi, lo;
        bfsplit2(v.x, v.y, hi, lo);
        xshiw[e*100 + kp] = hi;
        xslow[e*100 + kp] = lo;
    }
    __syncthreads();   /* smxs fp32 now dead -> vgbuf alias is safe */

    /* --- phase C: kt-major bf16x3 tensor GEMM; qc order {1,0,2} --- */
    unsigned xshi_s = (unsigned)__cvta_generic_to_shared(xshiw);
    unsigned xslo_s = (unsigned)__cvta_generic_to_shared(xslow);
    unsigned a_off  = (unsigned)((l & 15)*400 + (l >> 4)*16);

    #pragma unroll 1
    for (int qi = 0; qi < 3; qi++) {
        int qc = (qi == 0) ? 1 : (qi == 1 ? 0 : 2);
        float accP[2][4][4], accW[2][4][4];
        #pragma unroll
        for (int mt = 0; mt < 2; mt++)
            #pragma unroll
            for (int nt = 0; nt < 4; nt++)
                #pragma unroll
                for (int r = 0; r < 4; r++) { accP[mt][nt][r] = 0.f; accW[mt][nt][r] = 0.f; }

        const uint4* WB = g_WfHL + l;
        int recb = (qc*12)*16 + (w << 2);

        #pragma unroll 2
        for (int kt = 0; kt < 8; kt++) {          /* accP: k 0..127 */
            unsigned ah0[4], ah1[4], al0[4], al1[4];
            ldmA(ah0, xshi_s + a_off + kt*32);
            ldmA(ah1, xshi_s + a_off + kt*32 + 6400);
            ldmA(al0, xslo_s + a_off + kt*32);
            ldmA(al1, xslo_s + a_off + kt*32 + 6400);
            #pragma unroll
            for (int nt = 0; nt < 4; nt++) {
                uint4 bv = WB[(size_t)(recb + kt*16 + nt)*32];
                mmabf(accP[0][nt], ah0, bv.x, bv.y);
                mmabf(accP[1][nt], ah1, bv.x, bv.y);
                mmabf(accP[0][nt], ah0, bv.z, bv.w);
                mmabf(accP[1][nt], ah1, bv.z, bv.w);
                mmabf(accP[0][nt], al0, bv.x, bv.y);
                mmabf(accP[1][nt], al1, bv.x, bv.y);
            }
        }
        #pragma unroll 2
        for (int kt = 8; kt < 12; kt++) {         /* accW: k 128..191 */
            unsigned ah0[4], ah1[4], al0[4], al1[4];
            ldmA(ah0, xshi_s + a_off + kt*32);
            ldmA(ah1, xshi_s + a_off + kt*32 + 6400);
            ldmA(al0, xslo_s + a_off + kt*32);
            ldmA(al1, xslo_s + a_off + kt*32 + 6400);
            #pragma unroll
            for (int nt = 0; nt < 4; nt++) {
                uint4 bv = WB[(size_t)(recb + kt*16 + nt)*32];
                mmabf(accW[0][nt], ah0, bv.x, bv.y);
                mmabf(accW[1][nt], ah1, bv.x, bv.y);
                mmabf(accW[0][nt], ah0, bv.z, bv.w);
                mmabf(accW[1][nt], ah1, bv.z, bv.w);
                mmabf(accW[0][nt], al0, bv.x, bv.y);
                mmabf(accW[1][nt], al1, bv.x, bv.y);
            }
        }

        /* qc2 epilogue writes rgbuf (= xshiw/xslow region): wait until ALL
           warps finished their final MMAs reading xshi/xslo */
        if (qc == 2) __syncthreads();

        /* epilogue */
        #pragma unroll
        for (int nt = 0; nt < 4; nt++) {
            int ch0 = (w << 5) + (nt << 3) + ((l & 3) << 1);
            float2 bp = *(const float2*)&b_phi2[qc*128 + ch0];
            float2 bm = *(const float2*)&b_msg [qc*128 + ch0];
            #pragma unroll
            for (int mt = 0; mt < 2; mt++) {
                float m0 = (accP[mt][nt][0] + bp.x) * (accW[mt][nt][0] + bm.x);
                float m1 = (accP[mt][nt][1] + bp.y) * (accW[mt][nt][1] + bm.y);
                float m2 = (accP[mt][nt][2] + bp.x) * (accW[mt][nt][2] + bm.x);
                float m3 = (accP[mt][nt][3] + bp.y) * (accW[mt][nt][3] + bm.y);
                int e1 = (mt << 4) + (l >> 2);
                int e2 = e1 + 8;
                if (qc == 1) {
                    *(float2*)&vgbuf[e1*VGL + ch0] = make_float2(m0, m1);
                    *(float2*)&vgbuf[e2*VGL + ch0] = make_float2(m2, m3);
                } else if (qc == 2) {
                    *(float2*)&rgbuf[e1*VGL + ch0] = make_float2(m0, m1);
                    *(float2*)&rgbuf[e2*VGL + ch0] = make_float2(m2, m3);
                } else { /* qc == 0 : H scatter (sector-optimal) */
                    red2(out + (size_t)srow[e1]*128 + ch0, m0, m1);
                    red2(out + (size_t)srow[e2]*128 + ch0, m2, m3);
                }
            }
        }
    }

    /* --- cooperative V pass: coalesced gather + red4 scatter --- */
    __syncthreads();
    {
        int e   = t >> 2;
        int seg = t & 3;
        int row = srow[e], col = scol[e];
        float u0 = sunit[e*3+0], u1 = sunit[e*3+1], u2 = sunit[e*3+2];
        int r0 = seg % 3;
        float ua = (r0==0) ? u0 : ((r0==1) ? u1 : u2);
        float ub = (r0==0) ? u1 : ((r0==1) ? u2 : u0);
        float uc = (r0==0) ? u2 : ((r0==1) ? u0 : u1);
        const float* vrow = V + (size_t)col*384;
        float* op = out + HN + (size_t)row*384;
        const float* vgr = vgbuf + e*VGL;
        const float* rgr = rgbuf + e*VGL;
        int ch = (seg == 3) ? 4 : seg;
        int r  = r0;
        #pragma unroll
        for (int i = 0; i < 24; i++) {
            int fo = 4*seg + 16*i;
            float4 vb;
            if (type != 1) vb = *(const float4*)(vrow + fo);
            else           vb = make_float4(0.f, 0.f, 0.f, 0.f);
            float vga = vgr[ch], vgb2 = vgr[ch+1];
            float rga = rgr[ch], rgb2 = rgr[ch+1];
            float uA, uB, uC;
            if (i % 3 == 0)      { uA = ua; uB = ub; uC = uc; }
            else if (i % 3 == 1) { uA = ub; uB = uc; uC = ua; }
            else                 { uA = uc; uB = ua; uC = ub; }
            bool cB = (r == 2);
            bool cC = (r >= 1);
            float vg1 = cB ? vgb2 : vga, rg1 = cB ? rgb2 : rga;
            float vg2 = cC ? vgb2 : vga, rg2 = cC ? rgb2 : rga;
            float dx = vb.x*vga + uA*rga;
            float dy = vb.y*vg1 + uB*rg1;
            float dz = vb.z*vg2 + uC*rg2;
            float dw = vb.w*vgb2 + uA*rgb2;
            red4(op + fo, dx, dy, dz, dw);
            ch += (r == 2) ? 6 : 5;
            r   = (r == 2) ? 0 : r + 1;
        }
    }
}

/* ---------------- finalize ---------------- */
__global__ void k_fin(float* __restrict__ out,
                      const unsigned char* __restrict__ m2d,
                      const unsigned char* __restrict__ m3d, int total)
{
    int idx = blockIdx.x*256 + threadIdx.x;
    if (idx >= total) return;
    int i = (idx < HN) ? (idx >> 7) : ((idx - HN) / 384);
    float v = out[idx];
    v = fminf(fmaxf(v, -100.f), 100.f);
    bool keep = ((m2d[i] | m3d[i] | g_mask[i]) != 0);
    out[idx] = keep ? v : 0.f;
}

#define SMEM_EDGE ((32*XSL + 3200 + 3200 + 2*32 + 4*32 + 96 + 32) * sizeof(float))

extern "C" void kernel_launch(void* const* d_in, const int* in_sizes, int n_in,
                              void* d_out, int out_size)
{
    int o = (in_sizes[3] == 1) ? 1 : 0;
    const float* H      = (const float*)d_in[0];
    const float* V      = (const float*)d_in[1];
    const float* Z      = (const float*)d_in[2];
    const float* H2d    = (const float*)d_in[3+o];
    const unsigned char* m2d = (const unsigned char*)d_in[4+o];
    const int*   E2didx = (const int*)d_in[5+o];
    const float* E2dfeat= (const float*)d_in[6+o];
    const float* Z3d    = (const float*)d_in[7+o];
    const unsigned char* m3d = (const unsigned char*)d_in[8+o];
    const int*   Edidx  = (const int*)d_in[9+o];
    const float* Edval  = (const float*)d_in[10+o];
    const float* virt   = (const float*)d_in[11+o];
    const float* ETe    = (const float*)d_in[12+o];
    const float* Wrbf   = (const float*)d_in[13+o];
    const float* We2d   = (const float*)d_in[14+o];
    const float* Wi     = (const float*)d_in[15+o];
    const float* Wphi1  = (const float*)d_in[16+o];
    const float* bphi1  = (const float*)d_in[17+o];
    const float* Wphi2  = (const float*)d_in[18+o];
    const float* bphi2  = (const float*)d_in[19+o];
    const float* Wmsg   = (const float*)d_in[20+o];
    const float* bmsg   = (const float*)d_in[21+o];
    float* out = (float*)d_out;

    cudaMemsetAsync(d_out, 0, (size_t)out_size * sizeof(float));
    k_pre<<<339, 256>>>(Wi, Wphi1, bphi1, We2d, Wrbf, ETe, virt, Wphi2, Wmsg);
    k_maskset<<<782, 256>>>(Edidx);
    k_nproj<<<1250, 128>>>(H, H2d);
    cudaFuncSetAttribute(k_edge, cudaFuncAttributeMaxDynamicSharedMemorySize,
                         (int)SMEM_EDGE);
    k_edge<<<NBT, 128, SMEM_EDGE>>>(E2didx, E2dfeat, Edidx, Edval, Z, Z3d, V,
                                    bphi2, bmsg, out);
    k_fin<<<(HN + 3*HN + 255)/256, 256>>>(out, m2d, m3d, HN + 3*HN);
}